// round 1
// baseline (speedup 1.0000x reference)
#include <cuda_runtime.h>
#include <math.h>

// Problem constants
#define BATCH 4096
#define HDIM  256
#define KEXP  16
#define DDIM  512
#define IDIM  8
#define EDIM  64
#define LN_EPS 1e-5f

// Scratch (static __device__ allocations — allowed; no cudaMalloc)
__device__ float g_h1[(size_t)KEXP * BATCH * DDIM];     // [k][b][d]  128MB
__device__ float g_h2[(size_t)BATCH * KEXP * DDIM];     // [b][k][d]  128MB
__device__ float g_gates[BATCH * KEXP];

// ---------------------------------------------------------------------------
// Gating: logits = tanh(h_prev @ gw1 + gb1) @ gw2 + gb2 ; softmax over K
// One block = 16 batch rows, 256 threads.
// ---------------------------------------------------------------------------
__global__ __launch_bounds__(256) void k_gating(
    const float* __restrict__ h_prev, const float* __restrict__ gw1,
    const float* __restrict__ gb1, const float* __restrict__ gw2,
    const float* __restrict__ gb2)
{
    __shared__ float As[16][HDIM];   // 16KB: h_prev tile, then reused for tanh acts
    const int tid = threadIdx.x;
    const int b0  = blockIdx.x * 16;

    // load 16 rows of h_prev
    for (int i = tid; i < 16 * HDIM; i += 256)
        As[i / HDIM][i % HDIM] = h_prev[(size_t)(b0 + i / HDIM) * HDIM + (i % HDIM)];
    __syncthreads();

    // hidden layer: thread = column j, computes 16 rows
    float acc[16];
#pragma unroll
    for (int r = 0; r < 16; r++) acc[r] = 0.f;
    for (int i = 0; i < HDIM; i++) {
        float g = gw1[(size_t)i * HDIM + tid];
#pragma unroll
        for (int r = 0; r < 16; r++) acc[r] += As[r][i] * g;
    }
    float gb = gb1[tid];
    __syncthreads();
#pragma unroll
    for (int r = 0; r < 16; r++) As[r][tid] = tanhf(acc[r] + gb);
    __syncthreads();

    // logits: thread (r = tid>>4, k = tid&15)
    const int r = tid >> 4, kk = tid & 15;
    float lg = gb2[kk];
    for (int j = 0; j < HDIM; j++) lg += As[r][j] * gw2[j * KEXP + kk];

    // softmax over 16-lane groups
    float m = lg;
#pragma unroll
    for (int o = 8; o > 0; o >>= 1) m = fmaxf(m, __shfl_xor_sync(0xffffffffu, m, o, 16));
    float e = expf(lg - m);
    float s = e;
#pragma unroll
    for (int o = 8; o > 0; o >>= 1) s += __shfl_xor_sync(0xffffffffu, s, o, 16);
    g_gates[(b0 + r) * KEXP + kk] = e / s;
}

// ---------------------------------------------------------------------------
// MetaNet layer 1: h1[k][b][d] = tanh(x_ext[b,k]*w1[k,d] + b1[k,d])
// ---------------------------------------------------------------------------
__global__ __launch_bounds__(128) void k_h1(
    const float* __restrict__ x_ext, const float* __restrict__ w1,
    const float* __restrict__ b1)
{
    const int b = blockIdx.x, k = blockIdx.y;
    const int d0 = threadIdx.x * 4;
    const float s = x_ext[b * KEXP + k];
    float4 w = *(const float4*)&w1[k * DDIM + d0];
    float4 bb = *(const float4*)&b1[k * DDIM + d0];
    float4 o;
    o.x = tanhf(s * w.x + bb.x);
    o.y = tanhf(s * w.y + bb.y);
    o.z = tanhf(s * w.z + bb.z);
    o.w = tanhf(s * w.w + bb.w);
    *(float4*)&g_h1[(size_t)k * BATCH * DDIM + (size_t)b * DDIM + d0] = o;
}

// ---------------------------------------------------------------------------
// MetaNet layer 2: for expert k (blockIdx.z): h2 = tanh(h1[k] @ w2[k] + b2[k])
// Classic 128x128x16 register-tiled sgemm, 256 threads, 8x8 per thread.
// ---------------------------------------------------------------------------
__global__ __launch_bounds__(256) void k_gemm(
    const float* __restrict__ w2, const float* __restrict__ b2)
{
    const int kx = blockIdx.z;
    const float* __restrict__ A = g_h1 + (size_t)kx * BATCH * DDIM;   // [4096][512]
    const float* __restrict__ B = w2 + (size_t)kx * DDIM * DDIM;      // [512][512]

    __shared__ float As[16][128];
    __shared__ float Bs[16][128];

    const int tid = threadIdx.x;
    const int tr = tid >> 4;          // 0..15
    const int tc = tid & 15;          // 0..15
    const int aRow = tid >> 2;        // 0..63
    const int aCol = (tid & 3) << 2;  // 0,4,8,12
    const int bRow = tid >> 5;        // 0..7
    const int bCol = (tid & 31) << 2; // 0..124
    const int rowBase = blockIdx.y * 128;
    const int colBase = blockIdx.x * 128;

    float acc[8][8];
#pragma unroll
    for (int i = 0; i < 8; i++)
#pragma unroll
        for (int j = 0; j < 8; j++) acc[i][j] = 0.f;

    for (int kt = 0; kt < DDIM; kt += 16) {
#pragma unroll
        for (int r = 0; r < 2; r++) {
            float4 va = *(const float4*)&A[(size_t)(rowBase + aRow + r * 64) * DDIM + kt + aCol];
            As[aCol + 0][aRow + r * 64] = va.x;
            As[aCol + 1][aRow + r * 64] = va.y;
            As[aCol + 2][aRow + r * 64] = va.z;
            As[aCol + 3][aRow + r * 64] = va.w;
        }
#pragma unroll
        for (int r = 0; r < 2; r++) {
            *(float4*)&Bs[bRow + r * 8][bCol] =
                *(const float4*)&B[(size_t)(kt + bRow + r * 8) * DDIM + colBase + bCol];
        }
        __syncthreads();
#pragma unroll
        for (int kk = 0; kk < 16; kk++) {
            float a[8], bv[8];
            *(float4*)&a[0] = *(const float4*)&As[kk][tr * 8];
            *(float4*)&a[4] = *(const float4*)&As[kk][tr * 8 + 4];
            *(float4*)&bv[0] = *(const float4*)&Bs[kk][tc * 8];
            *(float4*)&bv[4] = *(const float4*)&Bs[kk][tc * 8 + 4];
#pragma unroll
            for (int i = 0; i < 8; i++)
#pragma unroll
                for (int j = 0; j < 8; j++) acc[i][j] += a[i] * bv[j];
        }
        __syncthreads();
    }

    // epilogue: +b2, tanh, store to g_h2[b][k][e]
    float bias[8];
    *(float4*)&bias[0] = *(const float4*)&b2[kx * DDIM + colBase + tc * 8];
    *(float4*)&bias[4] = *(const float4*)&b2[kx * DDIM + colBase + tc * 8 + 4];
#pragma unroll
    for (int i = 0; i < 8; i++) {
        const int row = rowBase + tr * 8 + i;
        float4 o1, o2;
        o1.x = tanhf(acc[i][0] + bias[0]);
        o1.y = tanhf(acc[i][1] + bias[1]);
        o1.z = tanhf(acc[i][2] + bias[2]);
        o1.w = tanhf(acc[i][3] + bias[3]);
        o2.x = tanhf(acc[i][4] + bias[4]);
        o2.y = tanhf(acc[i][5] + bias[5]);
        o2.z = tanhf(acc[i][6] + bias[6]);
        o2.w = tanhf(acc[i][7] + bias[7]);
        float* dst = &g_h2[(size_t)row * (KEXP * DDIM) + kx * DDIM + colBase + tc * 8];
        *(float4*)dst = o1;
        *(float4*)(dst + 4) = o2;
    }
}

// ---------------------------------------------------------------------------
// Epilogue: per (b,k) LayerNorm over 512, gate-weighted sum over k,
// + theta0, then x_prime = x_l @ theta. One block per batch row, 128 threads.
// ---------------------------------------------------------------------------
__global__ __launch_bounds__(128) void k_epilogue(
    const float* __restrict__ ln_g, const float* __restrict__ ln_b,
    const float* __restrict__ theta0, const float* __restrict__ x_l,
    float* __restrict__ out)
{
    const int b = blockIdx.x;
    const int tid = threadIdx.x;
    __shared__ float s_g[16];
    __shared__ float s_red[8];
    __shared__ float s_stats[2];
    __shared__ float theta_s[512];

    if (tid < 16) s_g[tid] = g_gates[b * KEXP + tid];

    const int d0 = tid * 4;
    float4 lg = *(const float4*)&ln_g[d0];
    float4 lb = *(const float4*)&ln_b[d0];
    float th[4] = {0.f, 0.f, 0.f, 0.f};
    __syncthreads();

    for (int k = 0; k < KEXP; k++) {
        float4 v = *(const float4*)&g_h2[(size_t)b * (KEXP * DDIM) + k * DDIM + d0];
        float s = v.x + v.y + v.z + v.w;
        float q = v.x * v.x + v.y * v.y + v.z * v.z + v.w * v.w;
#pragma unroll
        for (int o = 16; o > 0; o >>= 1) {
            s += __shfl_xor_sync(0xffffffffu, s, o);
            q += __shfl_xor_sync(0xffffffffu, q, o);
        }
        const int wid = tid >> 5, lane = tid & 31;
        if (lane == 0) { s_red[wid] = s; s_red[4 + wid] = q; }
        __syncthreads();
        if (tid == 0) {
            float S = s_red[0] + s_red[1] + s_red[2] + s_red[3];
            float Q = s_red[4] + s_red[5] + s_red[6] + s_red[7];
            float mu = S * (1.f / 512.f);
            float var = Q * (1.f / 512.f) - mu * mu;
            s_stats[0] = mu;
            s_stats[1] = rsqrtf(var + LN_EPS);
        }
        __syncthreads();
        const float mu = s_stats[0], rs = s_stats[1], gk = s_g[k];
        th[0] += gk * ((v.x - mu) * rs * lg.x + lb.x);
        th[1] += gk * ((v.y - mu) * rs * lg.y + lb.y);
        th[2] += gk * ((v.z - mu) * rs * lg.z + lb.z);
        th[3] += gk * ((v.w - mu) * rs * lg.w + lb.w);
    }

    float4 t0 = *(const float4*)&theta0[d0];
    th[0] += t0.x; th[1] += t0.y; th[2] += t0.z; th[3] += t0.w;

    // theta output lives after x_prime: out[BATCH*EDIM + b*512 + d]
    float4 ov = make_float4(th[0], th[1], th[2], th[3]);
    *(float4*)&out[(size_t)BATCH * EDIM + (size_t)b * DDIM + d0] = ov;
    theta_s[d0 + 0] = th[0];
    theta_s[d0 + 1] = th[1];
    theta_s[d0 + 2] = th[2];
    theta_s[d0 + 3] = th[3];
    __syncthreads();

    if (tid < EDIM) {
        float xp = 0.f;
#pragma unroll
        for (int i = 0; i < IDIM; i++)
            xp += x_l[b * IDIM + i] * theta_s[i * EDIM + tid];
        out[(size_t)b * EDIM + tid] = xp;
    }
}

// ---------------------------------------------------------------------------
extern "C" void kernel_launch(void* const* d_in, const int* in_sizes, int n_in,
                              void* d_out, int out_size)
{
    const float* h_prev = (const float*)d_in[0];
    const float* x_l    = (const float*)d_in[1];
    const float* x_ext  = (const float*)d_in[2];
    const float* w1     = (const float*)d_in[3];
    const float* b1     = (const float*)d_in[4];
    const float* w2     = (const float*)d_in[5];
    const float* b2     = (const float*)d_in[6];
    const float* gw1    = (const float*)d_in[7];
    const float* gb1    = (const float*)d_in[8];
    const float* gw2    = (const float*)d_in[9];
    const float* gb2    = (const float*)d_in[10];
    const float* ln_g   = (const float*)d_in[11];
    const float* ln_b   = (const float*)d_in[12];
    const float* theta0 = (const float*)d_in[13];
    float* out = (float*)d_out;

    k_gating<<<BATCH / 16, 256>>>(h_prev, gw1, gb1, gw2, gb2);
    k_h1<<<dim3(BATCH, KEXP), 128>>>(x_ext, w1, b1);
    k_gemm<<<dim3(DDIM / 128, BATCH / 128, KEXP), 256>>>(w2, b2);
    k_epilogue<<<BATCH, 128>>>(ln_g, ln_b, theta0, x_l, out);
}

// round 3
// speedup vs baseline: 1.8756x; 1.8756x over previous
#include <cuda_runtime.h>
#include <cuda_bf16.h>
#include <math.h>
#include <stdint.h>

#define BATCH 4096
#define HDIM  256
#define KEXP  16
#define DDIM  512
#define IDIM  8
#define EDIM  64
#define LN_EPS 1e-5f

// ---------------------------------------------------------------------------
// Scratch (__device__ globals; no cudaMalloc)
// ---------------------------------------------------------------------------
__device__ __nv_bfloat16 g_h1hi[(size_t)KEXP * BATCH * DDIM];  // 64MB  [k][b][d]
__device__ __nv_bfloat16 g_h1lo[(size_t)KEXP * BATCH * DDIM];  // 64MB
__device__ __nv_bfloat16 g_w2hi[(size_t)KEXP * DDIM * DDIM];   // 8MB   [k][e][d]
__device__ __nv_bfloat16 g_w2lo[(size_t)KEXP * DDIM * DDIM];   // 8MB
__device__ float g_h2[(size_t)BATCH * KEXP * DDIM];            // 128MB [b][k][d]
__device__ float g_gates[BATCH * KEXP];

// ---------------------------------------------------------------------------
// PTX helpers (all non-'a' features: cp.async sm_80+, ldmatrix sm_75+,
// mma.sync bf16 sm_80+)
// ---------------------------------------------------------------------------
__device__ __forceinline__ uint32_t smem_u32(const void* p) {
    uint32_t a;
    asm("{ .reg .u64 t; cvta.to.shared.u64 t, %1; cvt.u32.u64 %0, t; }"
        : "=r"(a) : "l"(p));
    return a;
}
__device__ __forceinline__ void cpasync16(uint32_t dst, const void* src) {
    asm volatile("cp.async.cg.shared.global [%0], [%1], 16;" :: "r"(dst), "l"(src));
}
#define CP_COMMIT() asm volatile("cp.async.commit_group;" ::: "memory")
#define CP_WAIT0()  asm volatile("cp.async.wait_group 0;" ::: "memory")
#define CP_WAIT1()  asm volatile("cp.async.wait_group 1;" ::: "memory")

__device__ __forceinline__ void ldsm4(uint32_t* r, uint32_t addr) {
    asm volatile("ldmatrix.sync.aligned.m8n8.x4.shared.b16 {%0,%1,%2,%3}, [%4];"
        : "=r"(r[0]), "=r"(r[1]), "=r"(r[2]), "=r"(r[3]) : "r"(addr));
}
__device__ __forceinline__ void mma16816(float* d, const uint32_t* a,
                                         const uint32_t* b) {
    asm volatile(
        "mma.sync.aligned.m16n8k16.row.col.f32.bf16.bf16.f32 "
        "{%0,%1,%2,%3}, {%4,%5,%6,%7}, {%8,%9}, {%0,%1,%2,%3};"
        : "+f"(d[0]), "+f"(d[1]), "+f"(d[2]), "+f"(d[3])
        : "r"(a[0]), "r"(a[1]), "r"(a[2]), "r"(a[3]), "r"(b[0]), "r"(b[1]));
}
__device__ __forceinline__ uint32_t pack_bf2(float a, float b) {
    __nv_bfloat16 ha = __float2bfloat16(a), hb = __float2bfloat16(b);
    return ((uint32_t)__bfloat16_as_ushort(hb) << 16) | (uint32_t)__bfloat16_as_ushort(ha);
}

// ---------------------------------------------------------------------------
// Gating: logits = tanh(h_prev @ gw1 + gb1) @ gw2 + gb2 ; softmax over K
// ---------------------------------------------------------------------------
__global__ __launch_bounds__(256) void k_gating(
    const float* __restrict__ h_prev, const float* __restrict__ gw1,
    const float* __restrict__ gb1, const float* __restrict__ gw2,
    const float* __restrict__ gb2)
{
    __shared__ float As[16][HDIM];
    const int tid = threadIdx.x;
    const int b0  = blockIdx.x * 16;

    for (int i = tid; i < 16 * HDIM; i += 256)
        As[i / HDIM][i % HDIM] = h_prev[(size_t)(b0 + i / HDIM) * HDIM + (i % HDIM)];
    __syncthreads();

    float acc[16];
#pragma unroll
    for (int r = 0; r < 16; r++) acc[r] = 0.f;
    for (int i = 0; i < HDIM; i++) {
        float g = gw1[(size_t)i * HDIM + tid];
#pragma unroll
        for (int r = 0; r < 16; r++) acc[r] += As[r][i] * g;
    }
    float gb = gb1[tid];
    __syncthreads();
#pragma unroll
    for (int r = 0; r < 16; r++) As[r][tid] = tanhf(acc[r] + gb);
    __syncthreads();

    const int r = tid >> 4, kk = tid & 15;
    float lg = gb2[kk];
    for (int j = 0; j < HDIM; j++) lg += As[r][j] * gw2[j * KEXP + kk];

    float m = lg;
#pragma unroll
    for (int o = 8; o > 0; o >>= 1) m = fmaxf(m, __shfl_xor_sync(0xffffffffu, m, o, 16));
    float e = expf(lg - m);
    float s = e;
#pragma unroll
    for (int o = 8; o > 0; o >>= 1) s += __shfl_xor_sync(0xffffffffu, s, o, 16);
    g_gates[(b0 + r) * KEXP + kk] = e / s;
}

// ---------------------------------------------------------------------------
// h1 split hi/lo bf16: h1[k][b][d] = tanh(x_ext[b,k]*w1[k,d] + b1[k,d])
// ---------------------------------------------------------------------------
__global__ __launch_bounds__(128) void k_h1p(
    const float* __restrict__ x_ext, const float* __restrict__ w1,
    const float* __restrict__ b1)
{
    const int b = blockIdx.x, k = blockIdx.y;
    const int d0 = threadIdx.x * 4;
    const float s = x_ext[b * KEXP + k];
    float4 w  = *(const float4*)&w1[k * DDIM + d0];
    float4 bb = *(const float4*)&b1[k * DDIM + d0];
    float v0 = tanhf(fmaf(s, w.x, bb.x));
    float v1 = tanhf(fmaf(s, w.y, bb.y));
    float v2 = tanhf(fmaf(s, w.z, bb.z));
    float v3 = tanhf(fmaf(s, w.w, bb.w));
    __nv_bfloat16 h0 = __float2bfloat16(v0), h1 = __float2bfloat16(v1);
    __nv_bfloat16 h2 = __float2bfloat16(v2), h3 = __float2bfloat16(v3);

    const size_t base = ((size_t)k * BATCH + b) * DDIM + d0;
    uint2 hv = make_uint2(
        ((uint32_t)__bfloat16_as_ushort(h1) << 16) | __bfloat16_as_ushort(h0),
        ((uint32_t)__bfloat16_as_ushort(h3) << 16) | __bfloat16_as_ushort(h2));
    uint2 lv = make_uint2(
        pack_bf2(v0 - __bfloat162float(h0), v1 - __bfloat162float(h1)),
        pack_bf2(v2 - __bfloat162float(h2), v3 - __bfloat162float(h3)));
    *(uint2*)&g_h1hi[base] = hv;
    *(uint2*)&g_h1lo[base] = lv;
}

// ---------------------------------------------------------------------------
// w2 transpose + hi/lo split: g_w2hi/lo row (k,e), K-dim = d (contiguous)
// ---------------------------------------------------------------------------
__global__ __launch_bounds__(256) void k_w2p(const float* __restrict__ w2)
{
    __shared__ float s[64][129];
    const int e0 = blockIdx.x * 64, k = blockIdx.y;
    const int tid = threadIdx.x;

    for (int dblk = 0; dblk < DDIM; dblk += 128) {
        for (int i = tid; i < 128 * 64; i += 256) {
            int dl = i >> 6, el = i & 63;
            s[el][dl] = w2[((size_t)k * DDIM + dblk + dl) * DDIM + e0 + el];
        }
        __syncthreads();

        const int el = tid >> 2, cp = tid & 3;
        uint32_t hi[16], lo[16];
#pragma unroll
        for (int j = 0; j < 16; j++) {
            float a = s[el][cp * 32 + 2 * j];
            float b = s[el][cp * 32 + 2 * j + 1];
            __nv_bfloat16 ha = __float2bfloat16(a), hb = __float2bfloat16(b);
            hi[j] = ((uint32_t)__bfloat16_as_ushort(hb) << 16) | __bfloat16_as_ushort(ha);
            lo[j] = pack_bf2(a - __bfloat162float(ha), b - __bfloat162float(hb));
        }
        const size_t base = ((size_t)k * DDIM + e0 + el) * DDIM + dblk + cp * 32;
        uint4* dh = (uint4*)&g_w2hi[base];
        dh[0] = make_uint4(hi[0], hi[1], hi[2], hi[3]);
        dh[1] = make_uint4(hi[4], hi[5], hi[6], hi[7]);
        dh[2] = make_uint4(hi[8], hi[9], hi[10], hi[11]);
        dh[3] = make_uint4(hi[12], hi[13], hi[14], hi[15]);
        uint4* dl2 = (uint4*)&g_w2lo[base];
        dl2[0] = make_uint4(lo[0], lo[1], lo[2], lo[3]);
        dl2[1] = make_uint4(lo[4], lo[5], lo[6], lo[7]);
        dl2[2] = make_uint4(lo[8], lo[9], lo[10], lo[11]);
        dl2[3] = make_uint4(lo[12], lo[13], lo[14], lo[15]);
        __syncthreads();
    }
}

// ---------------------------------------------------------------------------
// bf16x3 HMMA GEMM: per expert kx, h2 = tanh(h1 @ w2 + b2).
// CTA tile 128x128, 8 warps (warp tile 64x32), k-chunk 32, cp.async 2-stage.
// Smem rows padded to 80B -> conflict-free ldmatrix.
// Stage layout: Ahi[128][80] Alo Bhi Blo  (4 x 10240B = 40960B per stage).
// ---------------------------------------------------------------------------
#define STAGE_BYTES 40960
#define GSMEM (2 * STAGE_BYTES)

__global__ __launch_bounds__(256, 2) void k_gemm_mma(const float* __restrict__ b2)
{
    extern __shared__ char dsm[];
    const int n0 = blockIdx.x * 128;
    const int m0 = blockIdx.y * 128;
    const int kx = blockIdx.z;
    const int tid = threadIdx.x, lane = tid & 31, wid = tid >> 5;
    const int wm = wid >> 2, wn = wid & 3;
    const uint32_t sbase = smem_u32(dsm);

    // per-thread cp.async slots: 2048 segs of 16B per stage, 8 per thread
    const char* srcp[8];
    uint32_t dsto[8];
#pragma unroll
    for (int t = 0; t < 8; t++) {
        int idx = tid + t * 256;
        int tile = idx >> 9, row = (idx >> 2) & 127, seg = idx & 3;
        const char* base;
        if (tile == 0)
            base = (const char*)g_h1hi + ((size_t)(kx * BATCH + m0 + row)) * (DDIM * 2);
        else if (tile == 1)
            base = (const char*)g_h1lo + ((size_t)(kx * BATCH + m0 + row)) * (DDIM * 2);
        else if (tile == 2)
            base = (const char*)g_w2hi + ((size_t)(kx * DDIM + n0 + row)) * (DDIM * 2);
        else
            base = (const char*)g_w2lo + ((size_t)(kx * DDIM + n0 + row)) * (DDIM * 2);
        srcp[t] = base + seg * 16;
        dsto[t] = sbase + tile * 10240 + row * 80 + seg * 16;
    }

    float acc[4][4][4];
#pragma unroll
    for (int i = 0; i < 4; i++)
#pragma unroll
        for (int j = 0; j < 4; j++)
#pragma unroll
            for (int q = 0; q < 4; q++) acc[i][j][q] = 0.f;

    // ldmatrix base offsets
    const int arow = lane & 15, aseg = lane >> 4;
    const int brow = (lane & 7) + ((lane >> 4) & 1) * 8, bseg = (lane >> 3) & 1;
    const uint32_t offAhi = sbase + (wm * 64 + arow) * 80 + aseg * 16;
    const uint32_t offAlo = offAhi + 10240;
    const uint32_t offBhi = sbase + 20480 + (wn * 32 + brow) * 80 + bseg * 16;
    const uint32_t offBlo = offBhi + 10240;

    // prologue: stage 0, chunk 0
#pragma unroll
    for (int t = 0; t < 8; t++) cpasync16(dsto[t], srcp[t]);
    CP_COMMIT();

    for (int c = 0; c < 16; ++c) {
        if (c + 1 < 16) {
            const uint32_t so = ((c + 1) & 1) * STAGE_BYTES;
#pragma unroll
            for (int t = 0; t < 8; t++)
                cpasync16(dsto[t] + so, srcp[t] + (c + 1) * 64);
            CP_COMMIT();
            CP_WAIT1();
        } else {
            CP_WAIT0();
        }
        __syncthreads();

        const uint32_t so = (c & 1) * STAGE_BYTES;
#pragma unroll
        for (int ks = 0; ks < 2; ks++) {
            uint32_t bh[8], bl[8];
            ldsm4(bh,     offBhi + so + ks * 32);
            ldsm4(bh + 4, offBhi + so + ks * 32 + 16 * 80);
            ldsm4(bl,     offBlo + so + ks * 32);
            ldsm4(bl + 4, offBlo + so + ks * 32 + 16 * 80);
#pragma unroll
            for (int mi = 0; mi < 4; mi++) {
                uint32_t ah[4], al[4];
                ldsm4(ah, offAhi + so + ks * 32 + mi * 16 * 80);
                ldsm4(al, offAlo + so + ks * 32 + mi * 16 * 80);
#pragma unroll
                for (int ni = 0; ni < 4; ni++) {
                    mma16816(acc[mi][ni], ah, bh + ni * 2);
                    mma16816(acc[mi][ni], ah, bl + ni * 2);
                    mma16816(acc[mi][ni], al, bh + ni * 2);
                }
            }
        }
        __syncthreads();
    }

    // epilogue: + b2, tanh, store to g_h2[b][k][d]
    const int gid = lane >> 2, qid = lane & 3;
    const float* b2k = b2 + kx * DDIM + n0 + wn * 32;
#pragma unroll
    for (int ni = 0; ni < 4; ni++) {
        const int ncol = ni * 8 + 2 * qid;
        const float bv0 = __ldg(&b2k[ncol]), bv1 = __ldg(&b2k[ncol + 1]);
#pragma unroll
        for (int mi = 0; mi < 4; mi++) {
            const int m = m0 + wm * 64 + mi * 16 + gid;
            const size_t base = (size_t)m * (KEXP * DDIM) + kx * DDIM + n0 + wn * 32 + ncol;
            float2 v0, v1;
            v0.x = tanhf(acc[mi][ni][0] + bv0);
            v0.y = tanhf(acc[mi][ni][1] + bv1);
            v1.x = tanhf(acc[mi][ni][2] + bv0);
            v1.y = tanhf(acc[mi][ni][3] + bv1);
            *(float2*)&g_h2[base] = v0;
            *(float2*)&g_h2[base + (size_t)8 * (KEXP * DDIM)] = v1;
        }
    }
}

// ---------------------------------------------------------------------------
// Epilogue: per (b,k) LayerNorm over 512, gate-weighted sum, theta0, x_prime.
// ---------------------------------------------------------------------------
__global__ __launch_bounds__(128) void k_epilogue(
    const float* __restrict__ ln_g, const float* __restrict__ ln_b,
    const float* __restrict__ theta0, const float* __restrict__ x_l,
    float* __restrict__ out)
{
    const int b = blockIdx.x;
    const int tid = threadIdx.x;
    __shared__ float s_g[16];
    __shared__ float s_red[8];
    __shared__ float s_stats[2];
    __shared__ float theta_s[512];

    if (tid < 16) s_g[tid] = g_gates[b * KEXP + tid];

    const int d0 = tid * 4;
    float4 lg = *(const float4*)&ln_g[d0];
    float4 lb = *(const float4*)&ln_b[d0];
    float th[4] = {0.f, 0.f, 0.f, 0.f};
    __syncthreads();

    for (int k = 0; k < KEXP; k++) {
        float4 v = *(const float4*)&g_h2[(size_t)b * (KEXP * DDIM) + k * DDIM + d0];
        float s = v.x + v.y + v.z + v.w;
        float q = v.x * v.x + v.y * v.y + v.z * v.z + v.w * v.w;
#pragma unroll
        for (int o = 16; o > 0; o >>= 1) {
            s += __shfl_xor_sync(0xffffffffu, s, o);
            q += __shfl_xor_sync(0xffffffffu, q, o);
        }
        const int wid = tid >> 5, lane = tid & 31;
        if (lane == 0) { s_red[wid] = s; s_red[4 + wid] = q; }
        __syncthreads();
        if (tid == 0) {
            float S = s_red[0] + s_red[1] + s_red[2] + s_red[3];
            float Q = s_red[4] + s_red[5] + s_red[6] + s_red[7];
            float mu = S * (1.f / 512.f);
            float var = Q * (1.f / 512.f) - mu * mu;
            s_stats[0] = mu;
            s_stats[1] = rsqrtf(var + LN_EPS);
        }
        __syncthreads();
        const float mu = s_stats[0], rs = s_stats[1], gk = s_g[k];
        th[0] += gk * ((v.x - mu) * rs * lg.x + lb.x);
        th[1] += gk * ((v.y - mu) * rs * lg.y + lb.y);
        th[2] += gk * ((v.z - mu) * rs * lg.z + lb.z);
        th[3] += gk * ((v.w - mu) * rs * lg.w + lb.w);
    }

    float4 t0 = *(const float4*)&theta0[d0];
    th[0] += t0.x; th[1] += t0.y; th[2] += t0.z; th[3] += t0.w;

    float4 ov = make_float4(th[0], th[1], th[2], th[3]);
    *(float4*)&out[(size_t)BATCH * EDIM + (size_t)b * DDIM + d0] = ov;
    theta_s[d0 + 0] = th[0];
    theta_s[d0 + 1] = th[1];
    theta_s[d0 + 2] = th[2];
    theta_s[d0 + 3] = th[3];
    __syncthreads();

    if (tid < EDIM) {
        float xp = 0.f;
#pragma unroll
        for (int i = 0; i < IDIM; i++)
            xp += x_l[b * IDIM + i] * theta_s[i * EDIM + tid];
        out[(size_t)b * EDIM + tid] = xp;
    }
}

// ---------------------------------------------------------------------------
extern "C" void kernel_launch(void* const* d_in, const int* in_sizes, int n_in,
                              void* d_out, int out_size)
{
    const float* h_prev = (const float*)d_in[0];
    const float* x_l    = (const float*)d_in[1];
    const float* x_ext  = (const float*)d_in[2];
    const float* w1     = (const float*)d_in[3];
    const float* b1     = (const float*)d_in[4];
    const float* w2     = (const float*)d_in[5];
    const float* b2     = (const float*)d_in[6];
    const float* gw1    = (const float*)d_in[7];
    const float* gb1    = (const float*)d_in[8];
    const float* gw2    = (const float*)d_in[9];
    const float* gb2    = (const float*)d_in[10];
    const float* ln_g   = (const float*)d_in[11];
    const float* ln_b   = (const float*)d_in[12];
    const float* theta0 = (const float*)d_in[13];
    float* out = (float*)d_out;

    cudaFuncSetAttribute(k_gemm_mma, cudaFuncAttributeMaxDynamicSharedMemorySize, GSMEM);

    k_gating<<<BATCH / 16, 256>>>(h_prev, gw1, gb1, gw2, gb2);
    k_w2p<<<dim3(DDIM / 64, KEXP), 256>>>(w2);
    k_h1p<<<dim3(BATCH, KEXP), 128>>>(x_ext, w1, b1);
    k_gemm_mma<<<dim3(DDIM / 128, BATCH / 128, KEXP), 256, GSMEM>>>(b2);
    k_epilogue<<<BATCH, 128>>>(ln_g, ln_b, theta0, x_l, out);
}

// round 4
// speedup vs baseline: 2.1219x; 1.1313x over previous
#include <cuda_runtime.h>
#include <cuda_bf16.h>
#include <math.h>
#include <stdint.h>

#define BATCH 4096
#define HDIM  256
#define KEXP  16
#define DDIM  512
#define IDIM  8
#define EDIM  64
#define LN_EPS 1e-5f

// ---------------------------------------------------------------------------
// Scratch (__device__ globals; no cudaMalloc)
// ---------------------------------------------------------------------------
__device__ __nv_bfloat16 g_h1hi[(size_t)KEXP * BATCH * DDIM];  // 64MB  [k][b][d]
__device__ __nv_bfloat16 g_h1lo[(size_t)KEXP * BATCH * DDIM];  // 64MB
__device__ __nv_bfloat16 g_w2hi[(size_t)KEXP * DDIM * DDIM];   // 8MB   [k][e][d]
__device__ __nv_bfloat16 g_w2lo[(size_t)KEXP * DDIM * DDIM];   // 8MB
__device__ float g_h2[(size_t)BATCH * KEXP * DDIM];            // 128MB [b][k][d]
__device__ float g_gates[BATCH * KEXP];

// ---------------------------------------------------------------------------
// Helpers
// ---------------------------------------------------------------------------
__device__ __forceinline__ uint32_t smem_u32(const void* p) {
    uint32_t a;
    asm("{ .reg .u64 t; cvta.to.shared.u64 t, %1; cvt.u32.u64 %0, t; }"
        : "=r"(a) : "l"(p));
    return a;
}
__device__ __forceinline__ void cpasync16(uint32_t dst, const void* src) {
    asm volatile("cp.async.cg.shared.global [%0], [%1], 16;" :: "r"(dst), "l"(src));
}
#define CP_COMMIT() asm volatile("cp.async.commit_group;" ::: "memory")
#define CP_WAIT1()  asm volatile("cp.async.wait_group 1;" ::: "memory")

__device__ __forceinline__ void ldsm4(uint32_t* r, uint32_t addr) {
    asm volatile("ldmatrix.sync.aligned.m8n8.x4.shared.b16 {%0,%1,%2,%3}, [%4];"
        : "=r"(r[0]), "=r"(r[1]), "=r"(r[2]), "=r"(r[3]) : "r"(addr));
}
__device__ __forceinline__ void mma16816(float* d, const uint32_t* a,
                                         const uint32_t* b) {
    asm volatile(
        "mma.sync.aligned.m16n8k16.row.col.f32.bf16.bf16.f32 "
        "{%0,%1,%2,%3}, {%4,%5,%6,%7}, {%8,%9}, {%0,%1,%2,%3};"
        : "+f"(d[0]), "+f"(d[1]), "+f"(d[2]), "+f"(d[3])
        : "r"(a[0]), "r"(a[1]), "r"(a[2]), "r"(a[3]), "r"(b[0]), "r"(b[1]));
}
__device__ __forceinline__ uint32_t pack_bf2(float a, float b) {
    __nv_bfloat16 ha = __float2bfloat16(a), hb = __float2bfloat16(b);
    return ((uint32_t)__bfloat16_as_ushort(hb) << 16) | (uint32_t)__bfloat16_as_ushort(ha);
}
// fast tanh: 2 MUFU + fast div, rel err ~1e-6 (vs budget 1e-3)
__device__ __forceinline__ float ftanh(float x) {
    float ax = fabsf(x);
    float e  = __expf(-2.f * ax);
    float r  = __fdividef(1.f - e, 1.f + e);
    return copysignf(r, x);
}

// ---------------------------------------------------------------------------
// Merged prep kernel: blocks [0,4096) = h1 split, [4096,4352) = gating,
// [4352,4480) = w2 transpose+split. 256 threads each; parts run concurrently.
// ---------------------------------------------------------------------------
__global__ __launch_bounds__(256) void k_prep(
    const float* __restrict__ h_prev, const float* __restrict__ gw1,
    const float* __restrict__ gb1, const float* __restrict__ gw2,
    const float* __restrict__ gb2, const float* __restrict__ x_ext,
    const float* __restrict__ w1, const float* __restrict__ b1,
    const float* __restrict__ w2)
{
    __shared__ float smf[8256];   // 33KB, overlaid per part
    const int bi = blockIdx.x;
    const int tid = threadIdx.x;

    if (bi < BATCH) {
        // ---- h1 hi/lo split: b = bi, all 16 experts, 512 dims ----
        const int b = bi;
        if (tid < KEXP) smf[tid] = x_ext[b * KEXP + tid];
        __syncthreads();
#pragma unroll
        for (int i = 0; i < 8; i++) {
            const int j = tid + i * 256;       // 0..2047 quads
            const int k = j >> 7;
            const int d0 = (j & 127) * 4;
            const float s = smf[k];
            float4 w  = *(const float4*)&w1[k * DDIM + d0];
            float4 bb = *(const float4*)&b1[k * DDIM + d0];
            float v0 = ftanh(fmaf(s, w.x, bb.x));
            float v1 = ftanh(fmaf(s, w.y, bb.y));
            float v2 = ftanh(fmaf(s, w.z, bb.z));
            float v3 = ftanh(fmaf(s, w.w, bb.w));
            __nv_bfloat16 h0 = __float2bfloat16(v0), h1 = __float2bfloat16(v1);
            __nv_bfloat16 h2 = __float2bfloat16(v2), h3 = __float2bfloat16(v3);
            const size_t base = ((size_t)k * BATCH + b) * DDIM + d0;
            uint2 hv = make_uint2(
                ((uint32_t)__bfloat16_as_ushort(h1) << 16) | __bfloat16_as_ushort(h0),
                ((uint32_t)__bfloat16_as_ushort(h3) << 16) | __bfloat16_as_ushort(h2));
            uint2 lv = make_uint2(
                pack_bf2(v0 - __bfloat162float(h0), v1 - __bfloat162float(h1)),
                pack_bf2(v2 - __bfloat162float(h2), v3 - __bfloat162float(h3)));
            *(uint2*)&g_h1hi[base] = hv;
            *(uint2*)&g_h1lo[base] = lv;
        }
    } else if (bi < BATCH + 256) {
        // ---- gating: 16 batch rows per block ----
        float (*As)[HDIM] = (float(*)[HDIM])smf;   // 16x256 = 4096 floats
        const int b0 = (bi - BATCH) * 16;

        for (int i = tid; i < 16 * HDIM; i += 256)
            As[i / HDIM][i % HDIM] = h_prev[(size_t)(b0 + i / HDIM) * HDIM + (i % HDIM)];
        __syncthreads();

        float acc[16];
#pragma unroll
        for (int r = 0; r < 16; r++) acc[r] = 0.f;
        for (int i = 0; i < HDIM; i++) {
            float g = gw1[(size_t)i * HDIM + tid];
#pragma unroll
            for (int r = 0; r < 16; r++) acc[r] += As[r][i] * g;
        }
        float gb = gb1[tid];
        __syncthreads();
#pragma unroll
        for (int r = 0; r < 16; r++) As[r][tid] = ftanh(acc[r] + gb);
        __syncthreads();

        const int r = tid >> 4, kk = tid & 15;
        float lg = gb2[kk];
        for (int j = 0; j < HDIM; j++) lg += As[r][j] * gw2[j * KEXP + kk];

        float m = lg;
#pragma unroll
        for (int o = 8; o > 0; o >>= 1) m = fmaxf(m, __shfl_xor_sync(0xffffffffu, m, o, 16));
        float e = expf(lg - m);
        float s = e;
#pragma unroll
        for (int o = 8; o > 0; o >>= 1) s += __shfl_xor_sync(0xffffffffu, s, o, 16);
        g_gates[(b0 + r) * KEXP + kk] = e / s;
    } else {
        // ---- w2 transpose + hi/lo split ----
        float (*s)[129] = (float(*)[129])smf;      // 64x129 = 8256 floats
        const int j = bi - (BATCH + 256);
        const int e0 = (j & 7) * 64, k = j >> 3;

        for (int dblk = 0; dblk < DDIM; dblk += 128) {
            for (int i = tid; i < 128 * 64; i += 256) {
                int dl = i >> 6, el = i & 63;
                s[el][dl] = w2[((size_t)k * DDIM + dblk + dl) * DDIM + e0 + el];
            }
            __syncthreads();

            const int el = tid >> 2, cp = tid & 3;
            uint32_t hi[16], lo[16];
#pragma unroll
            for (int jj = 0; jj < 16; jj++) {
                float a = s[el][cp * 32 + 2 * jj];
                float b = s[el][cp * 32 + 2 * jj + 1];
                __nv_bfloat16 ha = __float2bfloat16(a), hb = __float2bfloat16(b);
                hi[jj] = ((uint32_t)__bfloat16_as_ushort(hb) << 16) | __bfloat16_as_ushort(ha);
                lo[jj] = pack_bf2(a - __bfloat162float(ha), b - __bfloat162float(hb));
            }
            const size_t base = ((size_t)k * DDIM + e0 + el) * DDIM + dblk + cp * 32;
            uint4* dh = (uint4*)&g_w2hi[base];
            dh[0] = make_uint4(hi[0], hi[1], hi[2], hi[3]);
            dh[1] = make_uint4(hi[4], hi[5], hi[6], hi[7]);
            dh[2] = make_uint4(hi[8], hi[9], hi[10], hi[11]);
            dh[3] = make_uint4(hi[12], hi[13], hi[14], hi[15]);
            uint4* dl2 = (uint4*)&g_w2lo[base];
            dl2[0] = make_uint4(lo[0], lo[1], lo[2], lo[3]);
            dl2[1] = make_uint4(lo[4], lo[5], lo[6], lo[7]);
            dl2[2] = make_uint4(lo[8], lo[9], lo[10], lo[11]);
            dl2[3] = make_uint4(lo[12], lo[13], lo[14], lo[15]);
            __syncthreads();
        }
    }
}

// ---------------------------------------------------------------------------
// bf16x3 HMMA GEMM: per expert kx, h2 = tanh(h1 @ w2 + b2).
// CTA tile 128x256, 512 threads (16 warps, warp tile 64x32), k-chunk 32,
// 3-stage cp.async ring, ONE __syncthreads per chunk.
// Stage (61440B): Ahi[128][80] @0, Alo @10240, Bhi[256][80] @20480, Blo @40960.
// ---------------------------------------------------------------------------
#define STAGE_BYTES 61440
#define GSMEM (3 * STAGE_BYTES)   // 184320

__global__ __launch_bounds__(512, 1) void k_gemm_mma(const float* __restrict__ b2)
{
    extern __shared__ char dsm[];
    const int n0 = blockIdx.x * 256;
    const int m0 = blockIdx.y * 128;
    const int kx = blockIdx.z;
    const int tid = threadIdx.x, lane = tid & 31, wid = tid >> 5;
    const int wm = wid >> 3, wn = wid & 7;
    const uint32_t sbase = smem_u32(dsm);

    // cp.async slots: 3072 segs of 16B per stage, 6 per thread
    const char* srcp[6];
    uint32_t dsto[6];
#pragma unroll
    for (int t = 0; t < 6; t++) {
        const int idx = tid + t * 512;
        if (idx < 1024) {
            const int tile = idx >> 9;             // 0=Ahi 1=Alo
            const int row  = (idx >> 2) & 127;
            const int seg  = idx & 3;
            const __nv_bfloat16* g = tile ? g_h1lo : g_h1hi;
            srcp[t] = (const char*)(g + ((size_t)(kx * BATCH + m0 + row)) * DDIM) + seg * 16;
            dsto[t] = sbase + tile * 10240 + row * 80 + seg * 16;
        } else {
            const int j = idx - 1024;
            const int tile = j >> 10;              // 0=Bhi 1=Blo
            const int row  = (j >> 2) & 255;
            const int seg  = j & 3;
            const __nv_bfloat16* g = tile ? g_w2lo : g_w2hi;
            srcp[t] = (const char*)(g + ((size_t)(kx * DDIM + n0 + row)) * DDIM) + seg * 16;
            dsto[t] = sbase + 20480 + tile * 20480 + row * 80 + seg * 16;
        }
    }

    float acc[4][4][4];
#pragma unroll
    for (int i = 0; i < 4; i++)
#pragma unroll
        for (int j = 0; j < 4; j++)
#pragma unroll
            for (int q = 0; q < 4; q++) acc[i][j][q] = 0.f;

    // ldmatrix base offsets (stage offset added at use)
    const int arow = lane & 15, aseg = lane >> 4;
    const int brow = (lane & 7) + ((lane >> 4) & 1) * 8, bseg = (lane >> 3) & 1;
    const uint32_t offAhi = sbase + (wm * 64 + arow) * 80 + aseg * 16;
    const uint32_t offAlo = offAhi + 10240;
    const uint32_t offBhi = sbase + 20480 + (wn * 32 + brow) * 80 + bseg * 16;
    const uint32_t offBlo = offBhi + 20480;

    // prologue: chunks 0,1 -> stages 0,1
#pragma unroll
    for (int t = 0; t < 6; t++) cpasync16(dsto[t], srcp[t]);
    CP_COMMIT();
#pragma unroll
    for (int t = 0; t < 6; t++) cpasync16(dsto[t] + STAGE_BYTES, srcp[t] + 64);
    CP_COMMIT();

    for (int c = 0; c < 16; ++c) {
        CP_WAIT1();            // chunk c landed (this thread's groups)
        __syncthreads();       // all threads' chunk-c data visible; frees buf (c+2)%3

        if (c + 2 < 16) {
            const uint32_t so2 = (uint32_t)((c + 2) % 3) * STAGE_BYTES;
            const int boff = (c + 2) * 64;
#pragma unroll
            for (int t = 0; t < 6; t++)
                cpasync16(dsto[t] + so2, srcp[t] + boff);
        }
        CP_COMMIT();           // exactly one group per iter (may be empty)

        const uint32_t so = (uint32_t)(c % 3) * STAGE_BYTES;
#pragma unroll
        for (int ks = 0; ks < 2; ks++) {
            uint32_t bh[8], bl[8];
            ldsm4(bh,     offBhi + so + ks * 32);
            ldsm4(bh + 4, offBhi + so + ks * 32 + 16 * 80);
            ldsm4(bl,     offBlo + so + ks * 32);
            ldsm4(bl + 4, offBlo + so + ks * 32 + 16 * 80);
#pragma unroll
            for (int mi = 0; mi < 4; mi++) {
                uint32_t ah[4], al[4];
                ldsm4(ah, offAhi + so + ks * 32 + mi * 16 * 80);
                ldsm4(al, offAlo + so + ks * 32 + mi * 16 * 80);
#pragma unroll
                for (int ni = 0; ni < 4; ni++) {
                    mma16816(acc[mi][ni], ah, bh + ni * 2);
                    mma16816(acc[mi][ni], ah, bl + ni * 2);
                    mma16816(acc[mi][ni], al, bh + ni * 2);
                }
            }
        }
    }

    // epilogue: + b2, tanh, store to g_h2[b][k][d]
    const int gid = lane >> 2, qid = lane & 3;
    const float* b2k = b2 + kx * DDIM + n0 + wn * 32;
#pragma unroll
    for (int ni = 0; ni < 4; ni++) {
        const int ncol = ni * 8 + 2 * qid;
        const float bv0 = __ldg(&b2k[ncol]), bv1 = __ldg(&b2k[ncol + 1]);
#pragma unroll
        for (int mi = 0; mi < 4; mi++) {
            const int m = m0 + wm * 64 + mi * 16 + gid;
            const size_t base = (size_t)m * (KEXP * DDIM) + kx * DDIM + n0 + wn * 32 + ncol;
            float2 v0, v1;
            v0.x = ftanh(acc[mi][ni][0] + bv0);
            v0.y = ftanh(acc[mi][ni][1] + bv1);
            v1.x = ftanh(acc[mi][ni][2] + bv0);
            v1.y = ftanh(acc[mi][ni][3] + bv1);
            *(float2*)&g_h2[base] = v0;
            *(float2*)&g_h2[base + (size_t)8 * (KEXP * DDIM)] = v1;
        }
    }
}

// ---------------------------------------------------------------------------
// Epilogue: warp-per-expert LN (shfl-only stats), gate-weighted sum, theta0,
// x_prime. One block (128 thr, 4 warps) per batch row; 3 block syncs total.
// ---------------------------------------------------------------------------
__global__ __launch_bounds__(128) void k_epilogue(
    const float* __restrict__ ln_g, const float* __restrict__ ln_b,
    const float* __restrict__ theta0, const float* __restrict__ x_l,
    float* __restrict__ out)
{
    const int b = blockIdx.x;
    const int tid = threadIdx.x, lane = tid & 31, w = tid >> 5;
    __shared__ float s_g[16];
    __shared__ float s_part[4][512];
    __shared__ float s_theta[512];

    if (tid < 16) s_g[tid] = g_gates[b * KEXP + tid];

    float4 lg[4], lb[4];
#pragma unroll
    for (int q = 0; q < 4; q++) {
        const int d = q * 128 + lane * 4;
        lg[q] = *(const float4*)&ln_g[d];
        lb[q] = *(const float4*)&ln_b[d];
    }
    float th[4][4];
#pragma unroll
    for (int q = 0; q < 4; q++)
#pragma unroll
        for (int j = 0; j < 4; j++) th[q][j] = 0.f;
    __syncthreads();

#pragma unroll
    for (int kk = 0; kk < 4; kk++) {
        const int k = w + kk * 4;
        const float* src = g_h2 + (size_t)b * (KEXP * DDIM) + k * DDIM;
        float4 v[4];
        float s = 0.f, qq = 0.f;
#pragma unroll
        for (int q = 0; q < 4; q++) {
            v[q] = *(const float4*)&src[q * 128 + lane * 4];
            s  += v[q].x + v[q].y + v[q].z + v[q].w;
            qq += v[q].x * v[q].x + v[q].y * v[q].y + v[q].z * v[q].z + v[q].w * v[q].w;
        }
#pragma unroll
        for (int o = 16; o > 0; o >>= 1) {
            s  += __shfl_xor_sync(0xffffffffu, s, o);
            qq += __shfl_xor_sync(0xffffffffu, qq, o);
        }
        const float mu = s * (1.f / 512.f);
        const float var = qq * (1.f / 512.f) - mu * mu;
        const float rs = rsqrtf(var + LN_EPS);
        const float gk = s_g[k];
#pragma unroll
        for (int q = 0; q < 4; q++) {
            th[q][0] += gk * ((v[q].x - mu) * rs * lg[q].x + lb[q].x);
            th[q][1] += gk * ((v[q].y - mu) * rs * lg[q].y + lb[q].y);
            th[q][2] += gk * ((v[q].z - mu) * rs * lg[q].z + lb[q].z);
            th[q][3] += gk * ((v[q].w - mu) * rs * lg[q].w + lb[q].w);
        }
    }

#pragma unroll
    for (int q = 0; q < 4; q++)
        *(float4*)&s_part[w][q * 128 + lane * 4] = make_float4(th[q][0], th[q][1], th[q][2], th[q][3]);
    __syncthreads();

    // combine 4 warp-partials + theta0; emit theta
    const int d0 = tid * 4;
    float4 p0 = *(float4*)&s_part[0][d0];
    float4 p1 = *(float4*)&s_part[1][d0];
    float4 p2 = *(float4*)&s_part[2][d0];
    float4 p3 = *(float4*)&s_part[3][d0];
    float4 t0 = *(const float4*)&theta0[d0];
    float4 t;
    t.x = p0.x + p1.x + p2.x + p3.x + t0.x;
    t.y = p0.y + p1.y + p2.y + p3.y + t0.y;
    t.z = p0.z + p1.z + p2.z + p3.z + t0.z;
    t.w = p0.w + p1.w + p2.w + p3.w + t0.w;
    *(float4*)&out[(size_t)BATCH * EDIM + (size_t)b * DDIM + d0] = t;
    *(float4*)&s_theta[d0] = t;
    __syncthreads();

    if (tid < EDIM) {
        float xp = 0.f;
#pragma unroll
        for (int i = 0; i < IDIM; i++)
            xp += x_l[b * IDIM + i] * s_theta[i * EDIM + tid];
        out[(size_t)b * EDIM + tid] = xp;
    }
}

// ---------------------------------------------------------------------------
extern "C" void kernel_launch(void* const* d_in, const int* in_sizes, int n_in,
                              void* d_out, int out_size)
{
    const float* h_prev = (const float*)d_in[0];
    const float* x_l    = (const float*)d_in[1];
    const float* x_ext  = (const float*)d_in[2];
    const float* w1     = (const float*)d_in[3];
    const float* b1     = (const float*)d_in[4];
    const float* w2     = (const float*)d_in[5];
    const float* b2     = (const float*)d_in[6];
    const float* gw1    = (const float*)d_in[7];
    const float* gb1    = (const float*)d_in[8];
    const float* gw2    = (const float*)d_in[9];
    const float* gb2    = (const float*)d_in[10];
    const float* ln_g   = (const float*)d_in[11];
    const float* ln_b   = (const float*)d_in[12];
    const float* theta0 = (const float*)d_in[13];
    float* out = (float*)d_out;

    cudaFuncSetAttribute(k_gemm_mma, cudaFuncAttributeMaxDynamicSharedMemorySize, GSMEM);

    k_prep<<<BATCH + 256 + 128, 256>>>(h_prev, gw1, gb1, gw2, gb2,
                                       x_ext, w1, b1, w2);
    k_gemm_mma<<<dim3(DDIM / 256, BATCH / 128, KEXP), 512, GSMEM>>>(b2);
    k_epilogue<<<BATCH, 128>>>(ln_g, ln_b, theta0, x_l, out);
}

// round 5
// speedup vs baseline: 2.1605x; 1.0182x over previous
#include <cuda_runtime.h>
#include <cuda_bf16.h>
#include <cuda_fp16.h>
#include <math.h>
#include <stdint.h>

#define BATCH 4096
#define HDIM  256
#define KEXP  16
#define DDIM  512
#define IDIM  8
#define EDIM  64
#define LN_EPS 1e-5f

// ---------------------------------------------------------------------------
// Scratch (__device__ globals; no cudaMalloc)
// ---------------------------------------------------------------------------
__device__ __nv_bfloat16 g_w2hi[(size_t)KEXP * DDIM * DDIM];   // 8MB   [k][e][d]
__device__ __nv_bfloat16 g_w2lo[(size_t)KEXP * DDIM * DDIM];   // 8MB
__device__ __half g_h2[(size_t)BATCH * KEXP * DDIM];           // 64MB [b][k][d]
__device__ float g_gates[BATCH * KEXP];

// ---------------------------------------------------------------------------
// Helpers
// ---------------------------------------------------------------------------
__device__ __forceinline__ uint32_t smem_u32(const void* p) {
    uint32_t a;
    asm("{ .reg .u64 t; cvta.to.shared.u64 t, %1; cvt.u32.u64 %0, t; }"
        : "=r"(a) : "l"(p));
    return a;
}
__device__ __forceinline__ void cpasync16(uint32_t dst, const void* src) {
    asm volatile("cp.async.cg.shared.global [%0], [%1], 16;" :: "r"(dst), "l"(src));
}
#define CP_COMMIT() asm volatile("cp.async.commit_group;" ::: "memory")
#define CP_WAIT1()  asm volatile("cp.async.wait_group 1;" ::: "memory")

__device__ __forceinline__ void ldsm4(uint32_t* r, uint32_t addr) {
    asm volatile("ldmatrix.sync.aligned.m8n8.x4.shared.b16 {%0,%1,%2,%3}, [%4];"
        : "=r"(r[0]), "=r"(r[1]), "=r"(r[2]), "=r"(r[3]) : "r"(addr));
}
__device__ __forceinline__ void mma16816(float* d, const uint32_t* a,
                                         const uint32_t* b) {
    asm volatile(
        "mma.sync.aligned.m16n8k16.row.col.f32.bf16.bf16.f32 "
        "{%0,%1,%2,%3}, {%4,%5,%6,%7}, {%8,%9}, {%0,%1,%2,%3};"
        : "+f"(d[0]), "+f"(d[1]), "+f"(d[2]), "+f"(d[3])
        : "r"(a[0]), "r"(a[1]), "r"(a[2]), "r"(a[3]), "r"(b[0]), "r"(b[1]));
}
__device__ __forceinline__ uint32_t pack_bf2(float a, float b) {
    __nv_bfloat16 ha = __float2bfloat16(a), hb = __float2bfloat16(b);
    return ((uint32_t)__bfloat16_as_ushort(hb) << 16) | (uint32_t)__bfloat16_as_ushort(ha);
}
// fast tanh: 2 MUFU + fast div, rel err ~1e-6
__device__ __forceinline__ float ftanh(float x) {
    float ax = fabsf(x);
    float e  = __expf(-2.f * ax);
    float r  = __fdividef(1.f - e, 1.f + e);
    return copysignf(r, x);
}

// ---------------------------------------------------------------------------
// Prep kernel: blocks [0,256) = gating, [256,384) = w2 transpose+split
// ---------------------------------------------------------------------------
__global__ __launch_bounds__(256) void k_prep(
    const float* __restrict__ h_prev, const float* __restrict__ gw1,
    const float* __restrict__ gb1, const float* __restrict__ gw2,
    const float* __restrict__ gb2, const float* __restrict__ w2)
{
    __shared__ float smf[8256];
    const int bi = blockIdx.x;
    const int tid = threadIdx.x;

    if (bi < 256) {
        // ---- gating: 16 batch rows per block ----
        float (*As)[HDIM] = (float(*)[HDIM])smf;
        const int b0 = bi * 16;

        for (int i = tid; i < 16 * HDIM; i += 256)
            As[i / HDIM][i % HDIM] = h_prev[(size_t)(b0 + i / HDIM) * HDIM + (i % HDIM)];
        __syncthreads();

        float acc[16];
#pragma unroll
        for (int r = 0; r < 16; r++) acc[r] = 0.f;
        for (int i = 0; i < HDIM; i++) {
            float g = gw1[(size_t)i * HDIM + tid];
#pragma unroll
            for (int r = 0; r < 16; r++) acc[r] += As[r][i] * g;
        }
        float gb = gb1[tid];
        __syncthreads();
#pragma unroll
        for (int r = 0; r < 16; r++) As[r][tid] = ftanh(acc[r] + gb);
        __syncthreads();

        const int r = tid >> 4, kk = tid & 15;
        float lg = gb2[kk];
        for (int j = 0; j < HDIM; j++) lg += As[r][j] * gw2[j * KEXP + kk];

        float m = lg;
#pragma unroll
        for (int o = 8; o > 0; o >>= 1) m = fmaxf(m, __shfl_xor_sync(0xffffffffu, m, o, 16));
        float e = expf(lg - m);
        float s = e;
#pragma unroll
        for (int o = 8; o > 0; o >>= 1) s += __shfl_xor_sync(0xffffffffu, s, o, 16);
        g_gates[(b0 + r) * KEXP + kk] = e / s;
    } else {
        // ---- w2 transpose + hi/lo split ----
        float (*s)[129] = (float(*)[129])smf;
        const int j = bi - 256;
        const int e0 = (j & 7) * 64, k = j >> 3;

        for (int dblk = 0; dblk < DDIM; dblk += 128) {
            for (int i = tid; i < 128 * 64; i += 256) {
                int dl = i >> 6, el = i & 63;
                s[el][dl] = w2[((size_t)k * DDIM + dblk + dl) * DDIM + e0 + el];
            }
            __syncthreads();

            const int el = tid >> 2, cp = tid & 3;
            uint32_t hi[16], lo[16];
#pragma unroll
            for (int jj = 0; jj < 16; jj++) {
                float a = s[el][cp * 32 + 2 * jj];
                float b = s[el][cp * 32 + 2 * jj + 1];
                __nv_bfloat16 ha = __float2bfloat16(a), hb = __float2bfloat16(b);
                hi[jj] = ((uint32_t)__bfloat16_as_ushort(hb) << 16) | __bfloat16_as_ushort(ha);
                lo[jj] = pack_bf2(a - __bfloat162float(ha), b - __bfloat162float(hb));
            }
            const size_t base = ((size_t)k * DDIM + e0 + el) * DDIM + dblk + cp * 32;
            uint4* dh = (uint4*)&g_w2hi[base];
            dh[0] = make_uint4(hi[0], hi[1], hi[2], hi[3]);
            dh[1] = make_uint4(hi[4], hi[5], hi[6], hi[7]);
            dh[2] = make_uint4(hi[8], hi[9], hi[10], hi[11]);
            dh[3] = make_uint4(hi[12], hi[13], hi[14], hi[15]);
            uint4* dl2 = (uint4*)&g_w2lo[base];
            dl2[0] = make_uint4(lo[0], lo[1], lo[2], lo[3]);
            dl2[1] = make_uint4(lo[4], lo[5], lo[6], lo[7]);
            dl2[2] = make_uint4(lo[8], lo[9], lo[10], lo[11]);
            dl2[3] = make_uint4(lo[12], lo[13], lo[14], lo[15]);
            __syncthreads();
        }
    }
}

// ---------------------------------------------------------------------------
// bf16x3 HMMA GEMM with fused A generation.
// CTA tile 128x256, 512 threads, k-chunk 32, 3-stage ring.
// Stage (61440B): Ahi[128][80] @0, Alo @10240, Bhi[256][80] @20480, Blo @40960.
// A is GENERATED in-kernel from x_ext (128 scalars) + w1/b1 rows (smem).
// B arrives via cp.async. h2 stored fp16.
// ---------------------------------------------------------------------------
#define STAGE_BYTES 61440
#define CONST_OFF   (3 * STAGE_BYTES)              // 184320
#define GSMEM       (CONST_OFF + 512 + 2048 + 2048) // 188928

__global__ __launch_bounds__(512, 1) void k_gemm_mma(
    const float* __restrict__ b2, const float* __restrict__ x_ext,
    const float* __restrict__ w1, const float* __restrict__ b1)
{
    extern __shared__ char dsm[];
    const int n0 = blockIdx.x * 256;
    const int m0 = blockIdx.y * 128;
    const int kx = blockIdx.z;
    const int tid = threadIdx.x, lane = tid & 31, wid = tid >> 5;
    const int wm = wid >> 3, wn = wid & 7;
    const uint32_t sbase = smem_u32(dsm);

    float* s_x  = (float*)(dsm + CONST_OFF);          // 128
    float* s_w1 = (float*)(dsm + CONST_OFF + 512);    // 512
    float* s_b1 = (float*)(dsm + CONST_OFF + 2560);   // 512

    // load constants
    if (tid < 128) s_x[tid] = x_ext[(size_t)(m0 + tid) * KEXP + kx];
    s_w1[tid] = w1[kx * DDIM + tid];
    s_b1[tid] = b1[kx * DDIM + tid];

    // cp.async B slots: 2048 segs of 16B per stage, 4 per thread
    const char* srcp[4];
    uint32_t dsto[4];
#pragma unroll
    for (int t = 0; t < 4; t++) {
        const int idx = tid + t * 512;
        const int tile = idx >> 10;              // 0=Bhi 1=Blo
        const int row  = (idx >> 2) & 255;
        const int seg  = idx & 3;
        const __nv_bfloat16* g = tile ? g_w2lo : g_w2hi;
        srcp[t] = (const char*)(g + ((size_t)(kx * DDIM + n0 + row)) * DDIM) + seg * 16;
        dsto[t] = sbase + 20480 + tile * 20480 + row * 80 + seg * 16;
    }

    // A-gen indices: thread -> (row, jgroup of 8)
    const int gr = tid >> 2;
    const int gj = (tid & 3) * 8;
    const uint32_t ga_hi = sbase + gr * 80 + (tid & 3) * 16;
    const uint32_t ga_lo = ga_hi + 10240;

    float acc[4][4][4];
#pragma unroll
    for (int i = 0; i < 4; i++)
#pragma unroll
        for (int j = 0; j < 4; j++)
#pragma unroll
            for (int q = 0; q < 4; q++) acc[i][j][q] = 0.f;

    const int arow = lane & 15, aseg = lane >> 4;
    const int brow = (lane & 7) + ((lane >> 4) & 1) * 8, bseg = (lane >> 3) & 1;
    const uint32_t offAhi = sbase + (wm * 64 + arow) * 80 + aseg * 16;
    const uint32_t offAlo = offAhi + 10240;
    const uint32_t offBhi = sbase + 20480 + (wn * 32 + brow) * 80 + bseg * 16;
    const uint32_t offBlo = offBhi + 20480;

    __syncthreads();   // consts visible

    // A-gen lambda (chunk c -> stage so)
    auto genA = [&](int c, uint32_t so) {
        const float x = s_x[gr];
        uint32_t hi[4], lo[4];
#pragma unroll
        for (int i = 0; i < 4; i++) {
            const int j = c * 32 + gj + 2 * i;
            float v0 = ftanh(fmaf(x, s_w1[j],     s_b1[j]));
            float v1 = ftanh(fmaf(x, s_w1[j + 1], s_b1[j + 1]));
            __nv_bfloat16 h0 = __float2bfloat16(v0), h1 = __float2bfloat16(v1);
            hi[i] = ((uint32_t)__bfloat16_as_ushort(h1) << 16) | __bfloat16_as_ushort(h0);
            lo[i] = pack_bf2(v0 - __bfloat162float(h0), v1 - __bfloat162float(h1));
        }
        *(uint4*)(dsm + (ga_hi - sbase) + so) = make_uint4(hi[0], hi[1], hi[2], hi[3]);
        *(uint4*)(dsm + (ga_lo - sbase) + so) = make_uint4(lo[0], lo[1], lo[2], lo[3]);
    };

    // prologue: chunks 0,1
    genA(0, 0);
    genA(1, STAGE_BYTES);
#pragma unroll
    for (int t = 0; t < 4; t++) cpasync16(dsto[t], srcp[t]);
    CP_COMMIT();
#pragma unroll
    for (int t = 0; t < 4; t++) cpasync16(dsto[t] + STAGE_BYTES, srcp[t] + 64);
    CP_COMMIT();

    for (int c = 0; c < 16; ++c) {
        CP_WAIT1();            // B chunk c landed
        __syncthreads();       // A chunk c visible; stage (c+2)%3 free

        if (c + 2 < 16) {
            const uint32_t so2 = (uint32_t)((c + 2) % 3) * STAGE_BYTES;
            genA(c + 2, so2);
            const int boff = (c + 2) * 64;
#pragma unroll
            for (int t = 0; t < 4; t++)
                cpasync16(dsto[t] + so2, srcp[t] + boff);
        }
        CP_COMMIT();

        const uint32_t so = (uint32_t)(c % 3) * STAGE_BYTES;
#pragma unroll
        for (int ks = 0; ks < 2; ks++) {
            uint32_t bh[8], bl[8];
            ldsm4(bh,     offBhi + so + ks * 32);
            ldsm4(bh + 4, offBhi + so + ks * 32 + 16 * 80);
            ldsm4(bl,     offBlo + so + ks * 32);
            ldsm4(bl + 4, offBlo + so + ks * 32 + 16 * 80);
#pragma unroll
            for (int mi = 0; mi < 4; mi++) {
                uint32_t ah[4], al[4];
                ldsm4(ah, offAhi + so + ks * 32 + mi * 16 * 80);
                ldsm4(al, offAlo + so + ks * 32 + mi * 16 * 80);
#pragma unroll
                for (int ni = 0; ni < 4; ni++) {
                    mma16816(acc[mi][ni], ah, bh + ni * 2);
                    mma16816(acc[mi][ni], ah, bl + ni * 2);
                    mma16816(acc[mi][ni], al, bh + ni * 2);
                }
            }
        }
    }

    // epilogue: + b2, tanh, store fp16 to g_h2[b][k][d]
    const int gid = lane >> 2, qid = lane & 3;
    const float* b2k = b2 + kx * DDIM + n0 + wn * 32;
#pragma unroll
    for (int ni = 0; ni < 4; ni++) {
        const int ncol = ni * 8 + 2 * qid;
        const float bv0 = __ldg(&b2k[ncol]), bv1 = __ldg(&b2k[ncol + 1]);
#pragma unroll
        for (int mi = 0; mi < 4; mi++) {
            const int m = m0 + wm * 64 + mi * 16 + gid;
            const size_t base = (size_t)m * (KEXP * DDIM) + kx * DDIM + n0 + wn * 32 + ncol;
            __half2 v0 = __floats2half2_rn(ftanh(acc[mi][ni][0] + bv0),
                                           ftanh(acc[mi][ni][1] + bv1));
            __half2 v1 = __floats2half2_rn(ftanh(acc[mi][ni][2] + bv0),
                                           ftanh(acc[mi][ni][3] + bv1));
            *(__half2*)&g_h2[base] = v0;
            *(__half2*)&g_h2[base + (size_t)8 * (KEXP * DDIM)] = v1;
        }
    }
}

// ---------------------------------------------------------------------------
// Epilogue: warp-per-expert LN, gate-weighted sum, theta0, x_prime.
// ---------------------------------------------------------------------------
__global__ __launch_bounds__(128) void k_epilogue(
    const float* __restrict__ ln_g, const float* __restrict__ ln_b,
    const float* __restrict__ theta0, const float* __restrict__ x_l,
    float* __restrict__ out)
{
    const int b = blockIdx.x;
    const int tid = threadIdx.x, lane = tid & 31, w = tid >> 5;
    __shared__ float s_g[16];
    __shared__ float s_part[4][512];
    __shared__ float s_theta[512];

    if (tid < 16) s_g[tid] = g_gates[b * KEXP + tid];

    float4 lg[4], lb[4];
#pragma unroll
    for (int q = 0; q < 4; q++) {
        const int d = q * 128 + lane * 4;
        lg[q] = *(const float4*)&ln_g[d];
        lb[q] = *(const float4*)&ln_b[d];
    }
    float th[4][4];
#pragma unroll
    for (int q = 0; q < 4; q++)
#pragma unroll
        for (int j = 0; j < 4; j++) th[q][j] = 0.f;
    __syncthreads();

#pragma unroll
    for (int kk = 0; kk < 4; kk++) {
        const int k = w + kk * 4;
        const __half* src = g_h2 + (size_t)b * (KEXP * DDIM) + k * DDIM;
        float4 v[4];
        float s = 0.f, qq = 0.f;
#pragma unroll
        for (int q = 0; q < 4; q++) {
            uint2 raw = *(const uint2*)&src[q * 128 + lane * 4];
            float2 f0 = __half22float2(*reinterpret_cast<__half2*>(&raw.x));
            float2 f1 = __half22float2(*reinterpret_cast<__half2*>(&raw.y));
            v[q] = make_float4(f0.x, f0.y, f1.x, f1.y);
            s  += v[q].x + v[q].y + v[q].z + v[q].w;
            qq += v[q].x * v[q].x + v[q].y * v[q].y + v[q].z * v[q].z + v[q].w * v[q].w;
        }
#pragma unroll
        for (int o = 16; o > 0; o >>= 1) {
            s  += __shfl_xor_sync(0xffffffffu, s, o);
            qq += __shfl_xor_sync(0xffffffffu, qq, o);
        }
        const float mu = s * (1.f / 512.f);
        const float var = qq * (1.f / 512.f) - mu * mu;
        const float rs = rsqrtf(var + LN_EPS);
        const float gk = s_g[k];
#pragma unroll
        for (int q = 0; q < 4; q++) {
            th[q][0] += gk * ((v[q].x - mu) * rs * lg[q].x + lb[q].x);
            th[q][1] += gk * ((v[q].y - mu) * rs * lg[q].y + lb[q].y);
            th[q][2] += gk * ((v[q].z - mu) * rs * lg[q].z + lb[q].z);
            th[q][3] += gk * ((v[q].w - mu) * rs * lg[q].w + lb[q].w);
        }
    }

#pragma unroll
    for (int q = 0; q < 4; q++)
        *(float4*)&s_part[w][q * 128 + lane * 4] = make_float4(th[q][0], th[q][1], th[q][2], th[q][3]);
    __syncthreads();

    const int d0 = tid * 4;
    float4 p0 = *(float4*)&s_part[0][d0];
    float4 p1 = *(float4*)&s_part[1][d0];
    float4 p2 = *(float4*)&s_part[2][d0];
    float4 p3 = *(float4*)&s_part[3][d0];
    float4 t0 = *(const float4*)&theta0[d0];
    float4 t;
    t.x = p0.x + p1.x + p2.x + p3.x + t0.x;
    t.y = p0.y + p1.y + p2.y + p3.y + t0.y;
    t.z = p0.z + p1.z + p2.z + p3.z + t0.z;
    t.w = p0.w + p1.w + p2.w + p3.w + t0.w;
    *(float4*)&out[(size_t)BATCH * EDIM + (size_t)b * DDIM + d0] = t;
    *(float4*)&s_theta[d0] = t;
    __syncthreads();

    if (tid < EDIM) {
        float xp = 0.f;
#pragma unroll
        for (int i = 0; i < IDIM; i++)
            xp += x_l[b * IDIM + i] * s_theta[i * EDIM + tid];
        out[(size_t)b * EDIM + tid] = xp;
    }
}

// ---------------------------------------------------------------------------
extern "C" void kernel_launch(void* const* d_in, const int* in_sizes, int n_in,
                              void* d_out, int out_size)
{
    const float* h_prev = (const float*)d_in[0];
    const float* x_l    = (const float*)d_in[1];
    const float* x_ext  = (const float*)d_in[2];
    const float* w1     = (const float*)d_in[3];
    const float* b1     = (const float*)d_in[4];
    const float* w2     = (const float*)d_in[5];
    const float* b2     = (const float*)d_in[6];
    const float* gw1    = (const float*)d_in[7];
    const float* gb1    = (const float*)d_in[8];
    const float* gw2    = (const float*)d_in[9];
    const float* gb2    = (const float*)d_in[10];
    const float* ln_g   = (const float*)d_in[11];
    const float* ln_b   = (const float*)d_in[12];
    const float* theta0 = (const float*)d_in[13];
    float* out = (float*)d_out;

    cudaFuncSetAttribute(k_gemm_mma, cudaFuncAttributeMaxDynamicSharedMemorySize, GSMEM);

    k_prep<<<384, 256>>>(h_prev, gw1, gb1, gw2, gb2, w2);
    k_gemm_mma<<<dim3(DDIM / 256, BATCH / 128, KEXP), 512, GSMEM>>>(b2, x_ext, w1, b1);
    k_epilogue<<<BATCH, 128>>>(ln_g, ln_b, theta0, x_l, out);
}

// round 6
// speedup vs baseline: 3.6162x; 1.6738x over previous
#include <cuda_runtime.h>
#include <cuda_bf16.h>
#include <cuda_fp16.h>
#include <math.h>
#include <stdint.h>

#define BATCH 4096
#define HDIM  256
#define KEXP  16
#define DDIM  512
#define IDIM  8
#define EDIM  64
#define LN_EPS 1e-5f

// ---------------------------------------------------------------------------
// Scratch (__device__ globals; no cudaMalloc)
// ---------------------------------------------------------------------------
__device__ __half g_w2h[(size_t)KEXP * DDIM * DDIM];   // 8MB  [k][e][d] fp16
__device__ __half g_h2[(size_t)BATCH * KEXP * DDIM];   // 64MB [b][k][d]
__device__ float g_gates[BATCH * KEXP];

// ---------------------------------------------------------------------------
// Helpers
// ---------------------------------------------------------------------------
__device__ __forceinline__ uint32_t smem_u32(const void* p) {
    uint32_t a;
    asm("{ .reg .u64 t; cvta.to.shared.u64 t, %1; cvt.u32.u64 %0, t; }"
        : "=r"(a) : "l"(p));
    return a;
}
__device__ __forceinline__ void cpasync16(uint32_t dst, const void* src) {
    asm volatile("cp.async.cg.shared.global [%0], [%1], 16;" :: "r"(dst), "l"(src));
}
#define CP_COMMIT() asm volatile("cp.async.commit_group;" ::: "memory")
#define CP_WAIT1()  asm volatile("cp.async.wait_group 1;" ::: "memory")

__device__ __forceinline__ void ldsm4(uint32_t* r, uint32_t addr) {
    asm volatile("ldmatrix.sync.aligned.m8n8.x4.shared.b16 {%0,%1,%2,%3}, [%4];"
        : "=r"(r[0]), "=r"(r[1]), "=r"(r[2]), "=r"(r[3]) : "r"(addr));
}
// fp16 x fp16 -> fp32 accum
__device__ __forceinline__ void mma16816h(float* d, const uint32_t* a,
                                          const uint32_t* b) {
    asm volatile(
        "mma.sync.aligned.m16n8k16.row.col.f32.f16.f16.f32 "
        "{%0,%1,%2,%3}, {%4,%5,%6,%7}, {%8,%9}, {%0,%1,%2,%3};"
        : "+f"(d[0]), "+f"(d[1]), "+f"(d[2]), "+f"(d[3])
        : "r"(a[0]), "r"(a[1]), "r"(a[2]), "r"(a[3]), "r"(b[0]), "r"(b[1]));
}
// fast tanh: 2 MUFU + fast div, rel err ~1e-6
__device__ __forceinline__ float ftanh(float x) {
    float ax = fabsf(x);
    float e  = __expf(-2.f * ax);
    float r  = __fdividef(1.f - e, 1.f + e);
    return copysignf(r, x);
}

// ---------------------------------------------------------------------------
// Prep kernel: blocks [0,256) = gating, [256,768) = w2 transpose -> fp16
// ---------------------------------------------------------------------------
__global__ __launch_bounds__(256) void k_prep(
    const float* __restrict__ h_prev, const float* __restrict__ gw1,
    const float* __restrict__ gb1, const float* __restrict__ gw2,
    const float* __restrict__ gb2, const float* __restrict__ w2)
{
    __shared__ float smf[8256];
    const int bi = blockIdx.x;
    const int tid = threadIdx.x;

    if (bi < 256) {
        // ---- gating: 16 batch rows per block ----
        float (*As)[HDIM] = (float(*)[HDIM])smf;
        const int b0 = bi * 16;

        for (int i = tid; i < 16 * HDIM; i += 256)
            As[i / HDIM][i % HDIM] = h_prev[(size_t)(b0 + i / HDIM) * HDIM + (i % HDIM)];
        __syncthreads();

        float acc[16];
#pragma unroll
        for (int r = 0; r < 16; r++) acc[r] = 0.f;
        for (int i = 0; i < HDIM; i++) {
            float g = gw1[(size_t)i * HDIM + tid];
#pragma unroll
            for (int r = 0; r < 16; r++) acc[r] += As[r][i] * g;
        }
        float gb = gb1[tid];
        __syncthreads();
#pragma unroll
        for (int r = 0; r < 16; r++) As[r][tid] = ftanh(acc[r] + gb);
        __syncthreads();

        const int r = tid >> 4, kk = tid & 15;
        float lg = gb2[kk];
        for (int j = 0; j < HDIM; j++) lg += As[r][j] * gw2[j * KEXP + kk];

        float m = lg;
#pragma unroll
        for (int o = 8; o > 0; o >>= 1) m = fmaxf(m, __shfl_xor_sync(0xffffffffu, m, o, 16));
        float e = expf(lg - m);
        float s = e;
#pragma unroll
        for (int o = 8; o > 0; o >>= 1) s += __shfl_xor_sync(0xffffffffu, s, o, 16);
        g_gates[(b0 + r) * KEXP + kk] = e / s;
    } else {
        // ---- w2 transpose to fp16: one 128d x 64e tile per block ----
        float (*s)[129] = (float(*)[129])smf;   // [e 64][d 128(+1)]
        const int j = bi - 256;                  // 0..511
        const int k = j >> 5;
        const int t = j & 31;
        const int e0 = (t & 7) * 64;
        const int dblk = (t >> 3) * 128;

        for (int i = tid; i < 128 * 64; i += 256) {
            int dl = i >> 6, el = i & 63;
            s[el][dl] = w2[((size_t)k * DDIM + dblk + dl) * DDIM + e0 + el];
        }
        __syncthreads();

        const int el = tid >> 2, cp = tid & 3;
        uint32_t hv[16];
#pragma unroll
        for (int jj = 0; jj < 16; jj++) {
            __half a = __float2half_rn(s[el][cp * 32 + 2 * jj]);
            __half b = __float2half_rn(s[el][cp * 32 + 2 * jj + 1]);
            hv[jj] = ((uint32_t)__half_as_ushort(b) << 16) | __half_as_ushort(a);
        }
        const size_t base = ((size_t)k * DDIM + e0 + el) * DDIM + dblk + cp * 32;
        uint4* dh = (uint4*)&g_w2h[base];
        dh[0] = make_uint4(hv[0], hv[1], hv[2], hv[3]);
        dh[1] = make_uint4(hv[4], hv[5], hv[6], hv[7]);
        dh[2] = make_uint4(hv[8], hv[9], hv[10], hv[11]);
        dh[3] = make_uint4(hv[12], hv[13], hv[14], hv[15]);
    }
}

// ---------------------------------------------------------------------------
// Single-pass fp16 HMMA GEMM with fused A generation.
// CTA tile 128x256, 512 threads (16 warps, warp tile 64x32), k-chunk 32,
// 3-stage ring. Stage (30720B): A[128][80] @0, B[256][80] @10240.
// A generated in-kernel: tanh(x_ext*w1+b1) -> fp16. B via cp.async (fp16 w2).
// ---------------------------------------------------------------------------
#define STAGE_BYTES 30720
#define CONST_OFF   (3 * STAGE_BYTES)               // 92160
#define GSMEM       (CONST_OFF + 512 + 2048 + 2048)  // 96768

__global__ __launch_bounds__(512, 1) void k_gemm_mma(
    const float* __restrict__ b2, const float* __restrict__ x_ext,
    const float* __restrict__ w1, const float* __restrict__ b1)
{
    extern __shared__ char dsm[];
    const int n0 = blockIdx.x * 256;
    const int m0 = blockIdx.y * 128;
    const int kx = blockIdx.z;
    const int tid = threadIdx.x, lane = tid & 31, wid = tid >> 5;
    const int wm = wid >> 3, wn = wid & 7;
    const uint32_t sbase = smem_u32(dsm);

    float* s_x  = (float*)(dsm + CONST_OFF);           // 128
    float* s_w1 = (float*)(dsm + CONST_OFF + 512);     // 512
    float* s_b1 = (float*)(dsm + CONST_OFF + 2560);    // 512

    if (tid < 128) s_x[tid] = x_ext[(size_t)(m0 + tid) * KEXP + kx];
    s_w1[tid] = w1[kx * DDIM + tid];
    s_b1[tid] = b1[kx * DDIM + tid];

    // cp.async B slots: 1024 segs of 16B per stage, 2 per thread
    const char* srcp[2];
    uint32_t dsto[2];
#pragma unroll
    for (int t = 0; t < 2; t++) {
        const int idx = tid + t * 512;
        const int row = idx >> 2;        // 0..255
        const int seg = idx & 3;
        srcp[t] = (const char*)(g_w2h + ((size_t)(kx * DDIM + n0 + row)) * DDIM) + seg * 16;
        dsto[t] = sbase + 10240 + row * 80 + seg * 16;
    }

    // A-gen indices
    const int gr = tid >> 2;
    const int gj = (tid & 3) * 8;
    const uint32_t ga = sbase + gr * 80 + (tid & 3) * 16;

    float acc[4][4][4];
#pragma unroll
    for (int i = 0; i < 4; i++)
#pragma unroll
        for (int j = 0; j < 4; j++)
#pragma unroll
            for (int q = 0; q < 4; q++) acc[i][j][q] = 0.f;

    const int arow = lane & 15, aseg = lane >> 4;
    const int brow = (lane & 7) + ((lane >> 4) & 1) * 8, bseg = (lane >> 3) & 1;
    const uint32_t offA = sbase + (wm * 64 + arow) * 80 + aseg * 16;
    const uint32_t offB = sbase + 10240 + (wn * 32 + brow) * 80 + bseg * 16;

    __syncthreads();   // consts visible

    auto genA = [&](int c, uint32_t so) {
        const float x = s_x[gr];
        uint32_t hv[4];
#pragma unroll
        for (int i = 0; i < 4; i++) {
            const int j = c * 32 + gj + 2 * i;
            float v0 = ftanh(fmaf(x, s_w1[j],     s_b1[j]));
            float v1 = ftanh(fmaf(x, s_w1[j + 1], s_b1[j + 1]));
            __half2 h = __floats2half2_rn(v0, v1);
            hv[i] = *reinterpret_cast<uint32_t*>(&h);
        }
        *(uint4*)(dsm + (ga - sbase) + so) = make_uint4(hv[0], hv[1], hv[2], hv[3]);
    };

    // prologue: chunks 0,1
    genA(0, 0);
    genA(1, STAGE_BYTES);
#pragma unroll
    for (int t = 0; t < 2; t++) cpasync16(dsto[t], srcp[t]);
    CP_COMMIT();
#pragma unroll
    for (int t = 0; t < 2; t++) cpasync16(dsto[t] + STAGE_BYTES, srcp[t] + 64);
    CP_COMMIT();

    for (int c = 0; c < 16; ++c) {
        CP_WAIT1();            // B chunk c landed
        __syncthreads();       // A chunk c visible; stage (c+2)%3 free

        if (c + 2 < 16) {
            const uint32_t so2 = (uint32_t)((c + 2) % 3) * STAGE_BYTES;
            genA(c + 2, so2);
            const int boff = (c + 2) * 64;
#pragma unroll
            for (int t = 0; t < 2; t++)
                cpasync16(dsto[t] + so2, srcp[t] + boff);
        }
        CP_COMMIT();

        const uint32_t so = (uint32_t)(c % 3) * STAGE_BYTES;
#pragma unroll
        for (int ks = 0; ks < 2; ks++) {
            uint32_t bh[8];
            ldsm4(bh,     offB + so + ks * 32);
            ldsm4(bh + 4, offB + so + ks * 32 + 16 * 80);
#pragma unroll
            for (int mi = 0; mi < 4; mi++) {
                uint32_t ah[4];
                ldsm4(ah, offA + so + ks * 32 + mi * 16 * 80);
#pragma unroll
                for (int ni = 0; ni < 4; ni++)
                    mma16816h(acc[mi][ni], ah, bh + ni * 2);
            }
        }
    }

    // epilogue: + b2, tanh, store fp16 to g_h2[b][k][d]
    const int gid = lane >> 2, qid = lane & 3;
    const float* b2k = b2 + kx * DDIM + n0 + wn * 32;
#pragma unroll
    for (int ni = 0; ni < 4; ni++) {
        const int ncol = ni * 8 + 2 * qid;
        const float bv0 = __ldg(&b2k[ncol]), bv1 = __ldg(&b2k[ncol + 1]);
#pragma unroll
        for (int mi = 0; mi < 4; mi++) {
            const int m = m0 + wm * 64 + mi * 16 + gid;
            const size_t base = (size_t)m * (KEXP * DDIM) + kx * DDIM + n0 + wn * 32 + ncol;
            __half2 v0 = __floats2half2_rn(ftanh(acc[mi][ni][0] + bv0),
                                           ftanh(acc[mi][ni][1] + bv1));
            __half2 v1 = __floats2half2_rn(ftanh(acc[mi][ni][2] + bv0),
                                           ftanh(acc[mi][ni][3] + bv1));
            *(__half2*)&g_h2[base] = v0;
            *(__half2*)&g_h2[base + (size_t)8 * (KEXP * DDIM)] = v1;
        }
    }
}

// ---------------------------------------------------------------------------
// Epilogue: warp-per-expert LN, gate-weighted sum, theta0, x_prime.
// ---------------------------------------------------------------------------
__global__ __launch_bounds__(128) void k_epilogue(
    const float* __restrict__ ln_g, const float* __restrict__ ln_b,
    const float* __restrict__ theta0, const float* __restrict__ x_l,
    float* __restrict__ out)
{
    const int b = blockIdx.x;
    const int tid = threadIdx.x, lane = tid & 31, w = tid >> 5;
    __shared__ float s_g[16];
    __shared__ float s_part[4][512];
    __shared__ float s_theta[512];

    if (tid < 16) s_g[tid] = g_gates[b * KEXP + tid];

    float4 lg[4], lb[4];
#pragma unroll
    for (int q = 0; q < 4; q++) {
        const int d = q * 128 + lane * 4;
        lg[q] = *(const float4*)&ln_g[d];
        lb[q] = *(const float4*)&ln_b[d];
    }
    float th[4][4];
#pragma unroll
    for (int q = 0; q < 4; q++)
#pragma unroll
        for (int j = 0; j < 4; j++) th[q][j] = 0.f;
    __syncthreads();

#pragma unroll
    for (int kk = 0; kk < 4; kk++) {
        const int k = w + kk * 4;
        const __half* src = g_h2 + (size_t)b * (KEXP * DDIM) + k * DDIM;
        float4 v[4];
        float s = 0.f, qq = 0.f;
#pragma unroll
        for (int q = 0; q < 4; q++) {
            uint2 raw = *(const uint2*)&src[q * 128 + lane * 4];
            float2 f0 = __half22float2(*reinterpret_cast<__half2*>(&raw.x));
            float2 f1 = __half22float2(*reinterpret_cast<__half2*>(&raw.y));
            v[q] = make_float4(f0.x, f0.y, f1.x, f1.y);
            s  += v[q].x + v[q].y + v[q].z + v[q].w;
            qq += v[q].x * v[q].x + v[q].y * v[q].y + v[q].z * v[q].z + v[q].w * v[q].w;
        }
#pragma unroll
        for (int o = 16; o > 0; o >>= 1) {
            s  += __shfl_xor_sync(0xffffffffu, s, o);
            qq += __shfl_xor_sync(0xffffffffu, qq, o);
        }
        const float mu = s * (1.f / 512.f);
        const float var = qq * (1.f / 512.f) - mu * mu;
        const float rs = rsqrtf(var + LN_EPS);
        const float gk = s_g[k];
#pragma unroll
        for (int q = 0; q < 4; q++) {
            th[q][0] += gk * ((v[q].x - mu) * rs * lg[q].x + lb[q].x);
            th[q][1] += gk * ((v[q].y - mu) * rs * lg[q].y + lb[q].y);
            th[q][2] += gk * ((v[q].z - mu) * rs * lg[q].z + lb[q].z);
            th[q][3] += gk * ((v[q].w - mu) * rs * lg[q].w + lb[q].w);
        }
    }

#pragma unroll
    for (int q = 0; q < 4; q++)
        *(float4*)&s_part[w][q * 128 + lane * 4] = make_float4(th[q][0], th[q][1], th[q][2], th[q][3]);
    __syncthreads();

    const int d0 = tid * 4;
    float4 p0 = *(float4*)&s_part[0][d0];
    float4 p1 = *(float4*)&s_part[1][d0];
    float4 p2 = *(float4*)&s_part[2][d0];
    float4 p3 = *(float4*)&s_part[3][d0];
    float4 t0 = *(const float4*)&theta0[d0];
    float4 t;
    t.x = p0.x + p1.x + p2.x + p3.x + t0.x;
    t.y = p0.y + p1.y + p2.y + p3.y + t0.y;
    t.z = p0.z + p1.z + p2.z + p3.z + t0.z;
    t.w = p0.w + p1.w + p2.w + p3.w + t0.w;
    *(float4*)&out[(size_t)BATCH * EDIM + (size_t)b * DDIM + d0] = t;
    *(float4*)&s_theta[d0] = t;
    __syncthreads();

    if (tid < EDIM) {
        float xp = 0.f;
#pragma unroll
        for (int i = 0; i < IDIM; i++)
            xp += x_l[b * IDIM + i] * s_theta[i * EDIM + tid];
        out[(size_t)b * EDIM + tid] = xp;
    }
}

// ---------------------------------------------------------------------------
extern "C" void kernel_launch(void* const* d_in, const int* in_sizes, int n_in,
                              void* d_out, int out_size)
{
    const float* h_prev = (const float*)d_in[0];
    const float* x_l    = (const float*)d_in[1];
    const float* x_ext  = (const float*)d_in[2];
    const float* w1     = (const float*)d_in[3];
    const float* b1     = (const float*)d_in[4];
    const float* w2     = (const float*)d_in[5];
    const float* b2     = (const float*)d_in[6];
    const float* gw1    = (const float*)d_in[7];
    const float* gb1    = (const float*)d_in[8];
    const float* gw2    = (const float*)d_in[9];
    const float* gb2    = (const float*)d_in[10];
    const float* ln_g   = (const float*)d_in[11];
    const float* ln_b   = (const float*)d_in[12];
    const float* theta0 = (const float*)d_in[13];
    float* out = (float*)d_out;

    cudaFuncSetAttribute(k_gemm_mma, cudaFuncAttributeMaxDynamicSharedMemorySize, GSMEM);

    k_prep<<<768, 256>>>(h_prev, gw1, gb1, gw2, gb2, w2);
    k_gemm_mma<<<dim3(DDIM / 256, BATCH / 128, KEXP), 512, GSMEM>>>(b2, x_ext, w1, b1);
    k_epilogue<<<BATCH, 128>>>(ln_g, ln_b, theta0, x_l, out);
}

// round 7
// speedup vs baseline: 3.8145x; 1.0548x over previous
#include <cuda_runtime.h>
#include <cuda_bf16.h>
#include <cuda_fp16.h>
#include <math.h>
#include <stdint.h>

#define BATCH 4096
#define HDIM  256
#define KEXP  16
#define DDIM  512
#define IDIM  8
#define EDIM  64
#define LN_EPS 1e-5f

// ---------------------------------------------------------------------------
// Scratch (__device__ globals; no cudaMalloc)
// ---------------------------------------------------------------------------
__device__ __half g_w2h[(size_t)KEXP * DDIM * DDIM];   // 8MB  [k][e][d] fp16
__device__ __half g_h2[(size_t)BATCH * KEXP * DDIM];   // 64MB [b][k][d]
__device__ float g_gates[BATCH * KEXP];

// ---------------------------------------------------------------------------
// Helpers
// ---------------------------------------------------------------------------
__device__ __forceinline__ uint32_t smem_u32(const void* p) {
    uint32_t a;
    asm("{ .reg .u64 t; cvta.to.shared.u64 t, %1; cvt.u32.u64 %0, t; }"
        : "=r"(a) : "l"(p));
    return a;
}
__device__ __forceinline__ void cpasync16(uint32_t dst, const void* src) {
    asm volatile("cp.async.cg.shared.global [%0], [%1], 16;" :: "r"(dst), "l"(src));
}
#define CP_COMMIT() asm volatile("cp.async.commit_group;" ::: "memory")
#define CP_WAIT1()  asm volatile("cp.async.wait_group 1;" ::: "memory")

__device__ __forceinline__ void ldsm4(uint32_t* r, uint32_t addr) {
    asm volatile("ldmatrix.sync.aligned.m8n8.x4.shared.b16 {%0,%1,%2,%3}, [%4];"
        : "=r"(r[0]), "=r"(r[1]), "=r"(r[2]), "=r"(r[3]) : "r"(addr));
}
// fp16 x fp16 -> fp32 accum
__device__ __forceinline__ void mma16816h(float* d, const uint32_t* a,
                                          const uint32_t* b) {
    asm volatile(
        "mma.sync.aligned.m16n8k16.row.col.f32.f16.f16.f32 "
        "{%0,%1,%2,%3}, {%4,%5,%6,%7}, {%8,%9}, {%0,%1,%2,%3};"
        : "+f"(d[0]), "+f"(d[1]), "+f"(d[2]), "+f"(d[3])
        : "r"(a[0]), "r"(a[1]), "r"(a[2]), "r"(a[3]), "r"(b[0]), "r"(b[1]));
}
// fast tanh: 2 MUFU + fast div, rel err ~1e-6
__device__ __forceinline__ float ftanh(float x) {
    float ax = fabsf(x);
    float e  = __expf(-2.f * ax);
    float r  = __fdividef(1.f - e, 1.f + e);
    return copysignf(r, x);
}

// ---------------------------------------------------------------------------
// Prep kernel: blocks [0,256) = gating, [256,768) = w2 transpose -> fp16
// ---------------------------------------------------------------------------
__global__ __launch_bounds__(256) void k_prep(
    const float* __restrict__ h_prev, const float* __restrict__ gw1,
    const float* __restrict__ gb1, const float* __restrict__ gw2,
    const float* __restrict__ gb2, const float* __restrict__ w2)
{
    __shared__ float smf[8256];
    const int bi = blockIdx.x;
    const int tid = threadIdx.x;

    if (bi < 256) {
        // ---- gating: 16 batch rows per block, MLP-8 prefetched loops ----
        float (*As)[HDIM] = (float(*)[HDIM])smf;
        const int b0 = bi * 16;

        for (int i = tid; i < 16 * HDIM; i += 256)
            As[i / HDIM][i % HDIM] = h_prev[(size_t)(b0 + i / HDIM) * HDIM + (i % HDIM)];
        __syncthreads();

        float acc[16];
#pragma unroll
        for (int r = 0; r < 16; r++) acc[r] = 0.f;
        for (int i0 = 0; i0 < HDIM; i0 += 8) {
            float g[8];
#pragma unroll
            for (int u = 0; u < 8; u++)
                g[u] = gw1[(size_t)(i0 + u) * HDIM + tid];
#pragma unroll
            for (int u = 0; u < 8; u++) {
                const float gg = g[u];
#pragma unroll
                for (int r = 0; r < 16; r++) acc[r] += As[r][i0 + u] * gg;
            }
        }
        float gb = gb1[tid];
        __syncthreads();
#pragma unroll
        for (int r = 0; r < 16; r++) As[r][tid] = ftanh(acc[r] + gb);
        __syncthreads();

        const int r = tid >> 4, kk = tid & 15;
        float lg = gb2[kk];
        for (int j0 = 0; j0 < HDIM; j0 += 8) {
            float g2[8];
#pragma unroll
            for (int u = 0; u < 8; u++)
                g2[u] = gw2[(j0 + u) * KEXP + kk];
#pragma unroll
            for (int u = 0; u < 8; u++)
                lg += As[r][j0 + u] * g2[u];
        }

        float m = lg;
#pragma unroll
        for (int o = 8; o > 0; o >>= 1) m = fmaxf(m, __shfl_xor_sync(0xffffffffu, m, o, 16));
        float e = expf(lg - m);
        float s = e;
#pragma unroll
        for (int o = 8; o > 0; o >>= 1) s += __shfl_xor_sync(0xffffffffu, s, o, 16);
        g_gates[(b0 + r) * KEXP + kk] = e / s;
    } else {
        // ---- w2 transpose to fp16: one 128d x 64e tile per block ----
        float (*s)[129] = (float(*)[129])smf;   // [e 64][d 128(+1)]
        const int j = bi - 256;                  // 0..511
        const int k = j >> 5;
        const int t = j & 31;
        const int e0 = (t & 7) * 64;
        const int dblk = (t >> 3) * 128;

        for (int i = tid; i < 128 * 64; i += 256) {
            int dl = i >> 6, el = i & 63;
            s[el][dl] = w2[((size_t)k * DDIM + dblk + dl) * DDIM + e0 + el];
        }
        __syncthreads();

        const int el = tid >> 2, cp = tid & 3;
        uint32_t hv[16];
#pragma unroll
        for (int jj = 0; jj < 16; jj++) {
            __half a = __float2half_rn(s[el][cp * 32 + 2 * jj]);
            __half b = __float2half_rn(s[el][cp * 32 + 2 * jj + 1]);
            hv[jj] = ((uint32_t)__half_as_ushort(b) << 16) | __half_as_ushort(a);
        }
        const size_t base = ((size_t)k * DDIM + e0 + el) * DDIM + dblk + cp * 32;
        uint4* dh = (uint4*)&g_w2h[base];
        dh[0] = make_uint4(hv[0], hv[1], hv[2], hv[3]);
        dh[1] = make_uint4(hv[4], hv[5], hv[6], hv[7]);
        dh[2] = make_uint4(hv[8], hv[9], hv[10], hv[11]);
        dh[3] = make_uint4(hv[12], hv[13], hv[14], hv[15]);
    }
}

// ---------------------------------------------------------------------------
// Single-pass fp16 HMMA GEMM with fused A generation.
// CTA tile 128x256, 512 threads (16 warps, warp tile 64x32), k-chunk 32,
// 3-stage ring. Stage (30720B): A[128][80] @0, B[256][80] @10240.
// ---------------------------------------------------------------------------
#define STAGE_BYTES 30720
#define CONST_OFF   (3 * STAGE_BYTES)               // 92160
#define GSMEM       (CONST_OFF + 512 + 2048 + 2048)  // 96768

__global__ __launch_bounds__(512, 1) void k_gemm_mma(
    const float* __restrict__ b2, const float* __restrict__ x_ext,
    const float* __restrict__ w1, const float* __restrict__ b1)
{
    extern __shared__ char dsm[];
    const int n0 = blockIdx.x * 256;
    const int m0 = blockIdx.y * 128;
    const int kx = blockIdx.z;
    const int tid = threadIdx.x, lane = tid & 31, wid = tid >> 5;
    const int wm = wid >> 3, wn = wid & 7;
    const uint32_t sbase = smem_u32(dsm);

    float* s_x  = (float*)(dsm + CONST_OFF);           // 128
    float* s_w1 = (float*)(dsm + CONST_OFF + 512);     // 512
    float* s_b1 = (float*)(dsm + CONST_OFF + 2560);    // 512

    if (tid < 128) s_x[tid] = x_ext[(size_t)(m0 + tid) * KEXP + kx];
    s_w1[tid] = w1[kx * DDIM + tid];
    s_b1[tid] = b1[kx * DDIM + tid];

    // cp.async B slots: 1024 segs of 16B per stage, 2 per thread
    const char* srcp[2];
    uint32_t dsto[2];
#pragma unroll
    for (int t = 0; t < 2; t++) {
        const int idx = tid + t * 512;
        const int row = idx >> 2;        // 0..255
        const int seg = idx & 3;
        srcp[t] = (const char*)(g_w2h + ((size_t)(kx * DDIM + n0 + row)) * DDIM) + seg * 16;
        dsto[t] = sbase + 10240 + row * 80 + seg * 16;
    }

    // A-gen indices
    const int gr = tid >> 2;
    const int gj = (tid & 3) * 8;
    const uint32_t ga = sbase + gr * 80 + (tid & 3) * 16;

    float acc[4][4][4];
#pragma unroll
    for (int i = 0; i < 4; i++)
#pragma unroll
        for (int j = 0; j < 4; j++)
#pragma unroll
            for (int q = 0; q < 4; q++) acc[i][j][q] = 0.f;

    const int arow = lane & 15, aseg = lane >> 4;
    const int brow = (lane & 7) + ((lane >> 4) & 1) * 8, bseg = (lane >> 3) & 1;
    const uint32_t offA = sbase + (wm * 64 + arow) * 80 + aseg * 16;
    const uint32_t offB = sbase + 10240 + (wn * 32 + brow) * 80 + bseg * 16;

    __syncthreads();   // consts visible

    auto genA = [&](int c, uint32_t so) {
        const float x = s_x[gr];
        uint32_t hv[4];
#pragma unroll
        for (int i = 0; i < 4; i++) {
            const int j = c * 32 + gj + 2 * i;
            float v0 = ftanh(fmaf(x, s_w1[j],     s_b1[j]));
            float v1 = ftanh(fmaf(x, s_w1[j + 1], s_b1[j + 1]));
            __half2 h = __floats2half2_rn(v0, v1);
            hv[i] = *reinterpret_cast<uint32_t*>(&h);
        }
        *(uint4*)(dsm + (ga - sbase) + so) = make_uint4(hv[0], hv[1], hv[2], hv[3]);
    };

    // prologue: chunks 0,1
    genA(0, 0);
    genA(1, STAGE_BYTES);
#pragma unroll
    for (int t = 0; t < 2; t++) cpasync16(dsto[t], srcp[t]);
    CP_COMMIT();
#pragma unroll
    for (int t = 0; t < 2; t++) cpasync16(dsto[t] + STAGE_BYTES, srcp[t] + 64);
    CP_COMMIT();

    for (int c = 0; c < 16; ++c) {
        CP_WAIT1();            // B chunk c landed
        __syncthreads();       // A chunk c visible; stage (c+2)%3 free

        if (c + 2 < 16) {
            const uint32_t so2 = (uint32_t)((c + 2) % 3) * STAGE_BYTES;
            genA(c + 2, so2);
            const int boff = (c + 2) * 64;
#pragma unroll
            for (int t = 0; t < 2; t++)
                cpasync16(dsto[t] + so2, srcp[t] + boff);
        }
        CP_COMMIT();

        const uint32_t so = (uint32_t)(c % 3) * STAGE_BYTES;
#pragma unroll
        for (int ks = 0; ks < 2; ks++) {
            uint32_t bh[8];
            ldsm4(bh,     offB + so + ks * 32);
            ldsm4(bh + 4, offB + so + ks * 32 + 16 * 80);
#pragma unroll
            for (int mi = 0; mi < 4; mi++) {
                uint32_t ah[4];
                ldsm4(ah, offA + so + ks * 32 + mi * 16 * 80);
#pragma unroll
                for (int ni = 0; ni < 4; ni++)
                    mma16816h(acc[mi][ni], ah, bh + ni * 2);
            }
        }
    }

    // epilogue: + b2, tanh, store fp16 to g_h2[b][k][d]
    const int gid = lane >> 2, qid = lane & 3;
    const float* b2k = b2 + kx * DDIM + n0 + wn * 32;
#pragma unroll
    for (int ni = 0; ni < 4; ni++) {
        const int ncol = ni * 8 + 2 * qid;
        const float bv0 = __ldg(&b2k[ncol]), bv1 = __ldg(&b2k[ncol + 1]);
#pragma unroll
        for (int mi = 0; mi < 4; mi++) {
            const int m = m0 + wm * 64 + mi * 16 + gid;
            const size_t base = (size_t)m * (KEXP * DDIM) + kx * DDIM + n0 + wn * 32 + ncol;
            __half2 v0 = __floats2half2_rn(ftanh(acc[mi][ni][0] + bv0),
                                           ftanh(acc[mi][ni][1] + bv1));
            __half2 v1 = __floats2half2_rn(ftanh(acc[mi][ni][2] + bv0),
                                           ftanh(acc[mi][ni][3] + bv1));
            *(__half2*)&g_h2[base] = v0;
            *(__half2*)&g_h2[base + (size_t)8 * (KEXP * DDIM)] = v1;
        }
    }
}

// ---------------------------------------------------------------------------
// Epilogue: warp-per-expert LN with all-expert prefetch (MLP 16),
// gate-weighted sum, theta0, x_prime.
// ---------------------------------------------------------------------------
__global__ __launch_bounds__(128) void k_epilogue(
    const float* __restrict__ ln_g, const float* __restrict__ ln_b,
    const float* __restrict__ theta0, const float* __restrict__ x_l,
    float* __restrict__ out)
{
    const int b = blockIdx.x;
    const int tid = threadIdx.x, lane = tid & 31, w = tid >> 5;
    __shared__ float s_g[16];
    __shared__ float s_part[4][512];
    __shared__ float s_theta[512];

    if (tid < 16) s_g[tid] = g_gates[b * KEXP + tid];

    // prefetch all 4 experts' raw data for this warp (MLP = 16)
    uint2 raw[4][4];
#pragma unroll
    for (int kk = 0; kk < 4; kk++) {
        const int k = w + kk * 4;
        const __half* src = g_h2 + (size_t)b * (KEXP * DDIM) + k * DDIM;
#pragma unroll
        for (int q = 0; q < 4; q++)
            raw[kk][q] = *(const uint2*)&src[q * 128 + lane * 4];
    }

    float4 lg[4], lb[4];
#pragma unroll
    for (int q = 0; q < 4; q++) {
        const int d = q * 128 + lane * 4;
        lg[q] = *(const float4*)&ln_g[d];
        lb[q] = *(const float4*)&ln_b[d];
    }
    float th[4][4];
#pragma unroll
    for (int q = 0; q < 4; q++)
#pragma unroll
        for (int j = 0; j < 4; j++) th[q][j] = 0.f;
    __syncthreads();

#pragma unroll
    for (int kk = 0; kk < 4; kk++) {
        const int k = w + kk * 4;
        float4 v[4];
        float s = 0.f, qq = 0.f;
#pragma unroll
        for (int q = 0; q < 4; q++) {
            float2 f0 = __half22float2(*reinterpret_cast<__half2*>(&raw[kk][q].x));
            float2 f1 = __half22float2(*reinterpret_cast<__half2*>(&raw[kk][q].y));
            v[q] = make_float4(f0.x, f0.y, f1.x, f1.y);
            s  += v[q].x + v[q].y + v[q].z + v[q].w;
            qq += v[q].x * v[q].x + v[q].y * v[q].y + v[q].z * v[q].z + v[q].w * v[q].w;
        }
#pragma unroll
        for (int o = 16; o > 0; o >>= 1) {
            s  += __shfl_xor_sync(0xffffffffu, s, o);
            qq += __shfl_xor_sync(0xffffffffu, qq, o);
        }
        const float mu = s * (1.f / 512.f);
        const float var = qq * (1.f / 512.f) - mu * mu;
        const float rs = rsqrtf(var + LN_EPS);
        const float gk = s_g[k];
#pragma unroll
        for (int q = 0; q < 4; q++) {
            th[q][0] += gk * ((v[q].x - mu) * rs * lg[q].x + lb[q].x);
            th[q][1] += gk * ((v[q].y - mu) * rs * lg[q].y + lb[q].y);
            th[q][2] += gk * ((v[q].z - mu) * rs * lg[q].z + lb[q].z);
            th[q][3] += gk * ((v[q].w - mu) * rs * lg[q].w + lb[q].w);
        }
    }

#pragma unroll
    for (int q = 0; q < 4; q++)
        *(float4*)&s_part[w][q * 128 + lane * 4] = make_float4(th[q][0], th[q][1], th[q][2], th[q][3]);
    __syncthreads();

    const int d0 = tid * 4;
    float4 p0 = *(float4*)&s_part[0][d0];
    float4 p1 = *(float4*)&s_part[1][d0];
    float4 p2 = *(float4*)&s_part[2][d0];
    float4 p3 = *(float4*)&s_part[3][d0];
    float4 t0 = *(const float4*)&theta0[d0];
    float4 t;
    t.x = p0.x + p1.x + p2.x + p3.x + t0.x;
    t.y = p0.y + p1.y + p2.y + p3.y + t0.y;
    t.z = p0.z + p1.z + p2.z + p3.z + t0.z;
    t.w = p0.w + p1.w + p2.w + p3.w + t0.w;
    *(float4*)&out[(size_t)BATCH * EDIM + (size_t)b * DDIM + d0] = t;
    *(float4*)&s_theta[d0] = t;
    __syncthreads();

    if (tid < EDIM) {
        float xp = 0.f;
#pragma unroll
        for (int i = 0; i < IDIM; i++)
            xp += x_l[b * IDIM + i] * s_theta[i * EDIM + tid];
        out[(size_t)b * EDIM + tid] = xp;
    }
}

// ---------------------------------------------------------------------------
extern "C" void kernel_launch(void* const* d_in, const int* in_sizes, int n_in,
                              void* d_out, int out_size)
{
    const float* h_prev = (const float*)d_in[0];
    const float* x_l    = (const float*)d_in[1];
    const float* x_ext  = (const float*)d_in[2];
    const float* w1     = (const float*)d_in[3];
    const float* b1     = (const float*)d_in[4];
    const float* w2     = (const float*)d_in[5];
    const float* b2     = (const float*)d_in[6];
    const float* gw1    = (const float*)d_in[7];
    const float* gb1    = (const float*)d_in[8];
    const float* gw2    = (const float*)d_in[9];
    const float* gb2    = (const float*)d_in[10];
    const float* ln_g   = (const float*)d_in[11];
    const float* ln_b   = (const float*)d_in[12];
    const float* theta0 = (const float*)d_in[13];
    float* out = (float*)d_out;

    cudaFuncSetAttribute(k_gemm_mma, cudaFuncAttributeMaxDynamicSharedMemorySize, GSMEM);

    k_prep<<<768, 256>>>(h_prev, gw1, gb1, gw2, gb2, w2);
    k_gemm_mma<<<dim3(DDIM / 256, BATCH / 128, KEXP), 512, GSMEM>>>(b2, x_ext, w1, b1);
    k_epilogue<<<BATCH, 128>>>(ln_g, ln_b, theta0, x_l, out);
}